// round 2
// baseline (speedup 1.0000x reference)
#include <cuda_runtime.h>
#include <cuda_bf16.h>

// ---------------- problem constants ----------------
#define L_SEQ    1024
#define D_MODEL  1024
#define D_INNER  2048
#define N_STATE  16
#define DT_RANK  64
#define K_CONV   4
#define X_DBL_W  96   // DT_RANK + 2*N_STATE

// ---------------- scratch (no cudaMalloc allowed) ----------------
__device__ float g_xr[L_SEQ * 2 * D_INNER];      // x_and_res [1024,4096]  16 MB
__device__ float g_xconv[L_SEQ * D_INNER];       // [1024,2048]             8 MB
__device__ float g_xdbl[L_SEQ * X_DBL_W];        // [1024,96]
__device__ float g_delta[L_SEQ * D_INNER];       // [1024,2048]             8 MB
__device__ float g_ysc[L_SEQ * D_INNER];         // (y + u*D)*silu(res)     8 MB

// ---------------- SGEMM: C[M,N] = A[M,K] @ B[K,N], row major ----------------
// 128x128 tile, BK=8, 256 threads, 8x8 per thread. All dims multiples of 128/8.
__global__ void sgemm128(const float* __restrict__ A, const float* __restrict__ B,
                         float* __restrict__ C, int M, int N, int K) {
    __shared__ float As[8][128];
    __shared__ float Bs[8][128];

    const int tid = threadIdx.x;            // 0..255
    const int bx = blockIdx.x;               // N tile
    const int by = blockIdx.y;               // M tile

    const int aRow  = tid >> 1;              // 0..127
    const int aCol4 = (tid & 1) * 4;         // 0 or 4
    const int bRow  = tid >> 5;              // 0..7
    const int bCol4 = (tid & 31) * 4;        // 0..124

    const int tx = tid & 15;
    const int ty = tid >> 4;

    const float* Ab = A + (size_t)(by * 128) * K;
    const float* Bb = B + bx * 128;

    float acc[8][8];
#pragma unroll
    for (int i = 0; i < 8; ++i)
#pragma unroll
        for (int j = 0; j < 8; ++j) acc[i][j] = 0.f;

    for (int k0 = 0; k0 < K; k0 += 8) {
        float4 a4 = *(const float4*)(Ab + (size_t)aRow * K + k0 + aCol4);
        As[aCol4 + 0][aRow] = a4.x;
        As[aCol4 + 1][aRow] = a4.y;
        As[aCol4 + 2][aRow] = a4.z;
        As[aCol4 + 3][aRow] = a4.w;
        float4 b4 = *(const float4*)(Bb + (size_t)(k0 + bRow) * N + bCol4);
        *(float4*)&Bs[bRow][bCol4] = b4;
        __syncthreads();

#pragma unroll
        for (int kk = 0; kk < 8; ++kk) {
            float ar[8], br[8];
            *(float4*)&ar[0] = *(const float4*)&As[kk][ty * 8];
            *(float4*)&ar[4] = *(const float4*)&As[kk][ty * 8 + 4];
            *(float4*)&br[0] = *(const float4*)&Bs[kk][tx * 8];
            *(float4*)&br[4] = *(const float4*)&Bs[kk][tx * 8 + 4];
#pragma unroll
            for (int i = 0; i < 8; ++i)
#pragma unroll
                for (int j = 0; j < 8; ++j)
                    acc[i][j] = fmaf(ar[i], br[j], acc[i][j]);
        }
        __syncthreads();
    }

#pragma unroll
    for (int i = 0; i < 8; ++i) {
        float* Cr = C + (size_t)(by * 128 + ty * 8 + i) * N + bx * 128 + tx * 8;
        float4 v0 = make_float4(acc[i][0], acc[i][1], acc[i][2], acc[i][3]);
        float4 v1 = make_float4(acc[i][4], acc[i][5], acc[i][6], acc[i][7]);
        *(float4*)(Cr + 0) = v0;
        *(float4*)(Cr + 4) = v1;
    }
}

// ---------------- causal depthwise conv (K=4) + SiLU ----------------
__global__ void conv_silu_kernel(const float* __restrict__ conv_w,
                                 const float* __restrict__ conv_b) {
    int idx = blockIdx.x * blockDim.x + threadIdx.x;   // 0 .. 1024*2048-1
    if (idx >= L_SEQ * D_INNER) return;
    int d = idx & (D_INNER - 1);
    int t = idx >> 11;                                  // /2048

    float w0 = conv_w[d * 4 + 0];
    float w1 = conv_w[d * 4 + 1];
    float w2 = conv_w[d * 4 + 2];
    float w3 = conv_w[d * 4 + 3];
    float s = conv_b[d];
    // x_in = g_xr[:, 0:2048]
    if (t - 3 >= 0) s += g_xr[(size_t)(t - 3) * 4096 + d] * w0;
    if (t - 2 >= 0) s += g_xr[(size_t)(t - 2) * 4096 + d] * w1;
    if (t - 1 >= 0) s += g_xr[(size_t)(t - 1) * 4096 + d] * w2;
    s += g_xr[(size_t)t * 4096 + d] * w3;

    float sig = 1.f / (1.f + __expf(-s));
    g_xconv[(size_t)t * D_INNER + d] = s * sig;
}

// ---------------- x_dbl = x_conv @ W_x   [1024,96] ----------------
__global__ void xdbl_kernel(const float* __restrict__ Wx) {
    int t = blockIdx.x;          // 0..1023
    int n = threadIdx.x;         // 0..95
    const float* xr = g_xconv + (size_t)t * D_INNER;
    float acc = 0.f;
#pragma unroll 8
    for (int k = 0; k < D_INNER; ++k)
        acc = fmaf(xr[k], Wx[(size_t)k * X_DBL_W + n], acc);
    g_xdbl[t * X_DBL_W + n] = acc;
}

// ---------------- delta = softplus(dt @ W_dt + b_dt)  [1024,2048] ----------------
__global__ void delta_kernel(const float* __restrict__ Wdt,
                             const float* __restrict__ bdt) {
    int d = blockIdx.x * 256 + threadIdx.x;   // 0..2047
    int t = blockIdx.y;                        // 0..1023

    __shared__ float dts[DT_RANK];
    if (threadIdx.x < DT_RANK) dts[threadIdx.x] = g_xdbl[t * X_DBL_W + threadIdx.x];
    __syncthreads();

    float acc = bdt[d];
#pragma unroll
    for (int k = 0; k < DT_RANK; ++k)
        acc = fmaf(dts[k], Wdt[(size_t)k * D_INNER + d], acc);

    // softplus
    float sp = (acc > 20.f) ? acc : log1pf(__expf(acc));
    g_delta[(size_t)t * D_INNER + d] = sp;
}

// ---------------- selective scan + gating epilogue ----------------
// thread = (channel d, state n).  h kept in register; 16-lane shfl reduction.
__global__ void scan_kernel(const float* __restrict__ A_log,
                            const float* __restrict__ Dp) {
    int tid = threadIdx.x;              // 128
    int g = tid >> 4;                    // 0..7 channel group within block
    int n = tid & 15;                    // state index
    int d = blockIdx.x * 8 + g;          // 0..2047

    float Aval = -__expf(A_log[d * N_STATE + n]);
    float Dd = Dp[d];
    float h = 0.f;

    for (int t = 0; t < L_SEQ; ++t) {
        float dl = g_delta[(size_t)t * D_INNER + d];
        float u  = g_xconv[(size_t)t * D_INNER + d];
        float Bv = g_xdbl[t * X_DBL_W + DT_RANK + n];
        float Cv = g_xdbl[t * X_DBL_W + DT_RANK + N_STATE + n];

        float dA = __expf(dl * Aval);
        h = fmaf(dA, h, dl * Bv * u);
        float part = h * Cv;
        part += __shfl_xor_sync(0xffffffffu, part, 8, 16);
        part += __shfl_xor_sync(0xffffffffu, part, 4, 16);
        part += __shfl_xor_sync(0xffffffffu, part, 2, 16);
        part += __shfl_xor_sync(0xffffffffu, part, 1, 16);

        if (n == 0) {
            float r = g_xr[(size_t)t * 4096 + D_INNER + d];   // res half
            float sr = r / (1.f + __expf(-r));                 // silu(res)
            g_ysc[(size_t)t * D_INNER + d] = (part + u * Dd) * sr;
        }
    }
}

// ---------------- launch ----------------
static float* sym_addr(const void* sym) {
    void* p = nullptr;
    cudaGetSymbolAddress(&p, sym);
    return (float*)p;
}

extern "C" void kernel_launch(void* const* d_in, const int* in_sizes, int n_in,
                              void* d_out, int out_size) {
    const float* x      = (const float*)d_in[0];
    const float* W_in   = (const float*)d_in[1];
    const float* conv_w = (const float*)d_in[2];
    const float* conv_b = (const float*)d_in[3];
    const float* W_x    = (const float*)d_in[4];
    const float* W_dt   = (const float*)d_in[5];
    const float* b_dt   = (const float*)d_in[6];
    const float* A_log  = (const float*)d_in[7];
    const float* Dvec   = (const float*)d_in[8];
    const float* W_out  = (const float*)d_in[9];
    float* out = (float*)d_out;

    float* xr    = sym_addr(g_xr);
    float* ysc   = sym_addr(g_ysc);

    // 1) x_and_res = x @ W_in    [1024,1024] x [1024,4096]
    sgemm128<<<dim3(4096 / 128, 1024 / 128), 256>>>(x, W_in, xr, 1024, 4096, 1024);

    // 2) conv + silu -> g_xconv
    conv_silu_kernel<<<(L_SEQ * D_INNER + 255) / 256, 256>>>(conv_w, conv_b);

    // 3) x_dbl = x_conv @ W_x
    xdbl_kernel<<<L_SEQ, X_DBL_W>>>(W_x);

    // 4) delta = softplus(dt @ W_dt + b_dt)
    delta_kernel<<<dim3(D_INNER / 256, L_SEQ), 256>>>(W_dt, b_dt);

    // 5) selective scan + D skip + silu(res) gating -> g_ysc
    scan_kernel<<<D_INNER / 8, 128>>>(A_log, Dvec);

    // 6) out = ysc @ W_out   [1024,2048] x [2048,1024]
    sgemm128<<<dim3(1024 / 128, 1024 / 128), 256>>>(ysc, W_out, out, 1024, 1024, 2048);
}

// round 6
// speedup vs baseline: 1.1404x; 1.1404x over previous
#include <cuda_runtime.h>
#include <cuda_fp16.h>
#include <cstdint>

// ---------------- problem constants ----------------
#define L_SEQ    1024
#define D_MODEL  1024
#define D_INNER  2048
#define N_STATE  16
#define DT_RANK  64
#define X_DBL_W  96   // DT_RANK + 2*N_STATE

// ---------------- fp32 scratch ----------------
__device__ float g_xr[L_SEQ * 2 * D_INNER];      // x_and_res [1024,4096]
__device__ float g_xconv[L_SEQ * D_INNER];       // [1024,2048]
__device__ float g_xdbl[L_SEQ * X_DBL_W];        // [1024,96]
__device__ float g_delta[L_SEQ * D_INNER];       // [1024,2048]
__device__ float g_ysc[L_SEQ * D_INNER];         // (y+u*D)*silu(res)

// ---------------- fp16 split-K scratch ----------------
// A_ext = [Ah | Ah | Al]  (M x 3K), B_ext = [Bh | Bl | Bh]  (N x 3K)
__device__ __half g_aext[1024 * 6144];           // max: ysc split (1024 x 3*2048)
__device__ __half g_b1e[4096 * 3072];            // W_in^T split
__device__ __half g_b2e[1024 * 6144];            // W_out^T split

// =====================================================================
// base-PTX helpers (compute_103-safe: ldmatrix / mma.sync / cp.async)
// =====================================================================
__device__ __forceinline__ uint32_t smem_u32(const void* p) {
    uint32_t a;
    asm("{ .reg .u64 t; cvta.to.shared.u64 t, %1; cvt.u32.u64 %0, t; }" : "=r"(a) : "l"(p));
    return a;
}
__device__ __forceinline__ void cp16(uint32_t s, const void* g) {
    asm volatile("cp.async.cg.shared.global [%0], [%1], 16;" :: "r"(s), "l"(g));
}
#define CP_COMMIT() asm volatile("cp.async.commit_group;" ::: "memory")

#define LDSM_X4(r0, r1, r2, r3, addr) \
    asm volatile("ldmatrix.sync.aligned.m8n8.x4.shared.b16 {%0,%1,%2,%3}, [%4];" \
        : "=r"(r0), "=r"(r1), "=r"(r2), "=r"(r3) : "r"(addr))
#define LDSM_X2(r0, r1, addr) \
    asm volatile("ldmatrix.sync.aligned.m8n8.x2.shared.b16 {%0,%1}, [%2];" \
        : "=r"(r0), "=r"(r1) : "r"(addr))
#define MMA16816(d, a, b) \
    asm volatile("mma.sync.aligned.m16n8k16.row.col.f32.f16.f16.f32 " \
        "{%0,%1,%2,%3}, {%4,%5,%6,%7}, {%8,%9}, {%0,%1,%2,%3};" \
        : "+f"((d)[0]), "+f"((d)[1]), "+f"((d)[2]), "+f"((d)[3]) \
        : "r"((a)[0]), "r"((a)[1]), "r"((a)[2]), "r"((a)[3]), "r"((b)[0]), "r"((b)[1]))

// =====================================================================
// HMMA GEMM: C[M,N] = A[M,K] @ B[N,K]^T, both fp16 row-major, fp32 out
// tile 128x128x32, 8 warps (warp tile 64x32), cp.async double buffer
// =====================================================================
#define GBM 128
#define GBN 128
#define GBK 32
#define A_STRIDE_B 80              // bytes per smem row (32 halves + 8 pad)
#define STAGE_B (GBM * A_STRIDE_B + GBN * A_STRIDE_B)   // 20480

__global__ void __launch_bounds__(256, 2) gemm_mma(
    const __half* __restrict__ A, const __half* __restrict__ B,
    float* __restrict__ C, int M, int N, int K) {
    __shared__ __align__(16) char smem[2 * STAGE_B];
    const uint32_t sbase = smem_u32(smem);
    const int tid = threadIdx.x;
    const int lane = tid & 31, wid = tid >> 5;
    const int m0 = blockIdx.y * GBM, n0 = blockIdx.x * GBN;
    const __half* Ag = A + (size_t)m0 * K;
    const __half* Bg = B + (size_t)n0 * K;

    const int wm = (wid & 1) * 64;
    const int wn = (wid >> 1) * 32;

    float acc[4][4][4];
#pragma unroll
    for (int i = 0; i < 4; ++i)
#pragma unroll
        for (int j = 0; j < 4; ++j)
#pragma unroll
            for (int q = 0; q < 4; ++q) acc[i][j][q] = 0.f;

    const int nIter = K >> 5;

    // prefetch tile 0
    {
        uint32_t sA = sbase, sB = sbase + GBM * A_STRIDE_B;
#pragma unroll
        for (int c = tid; c < 512; c += 256) {
            int r = c >> 2, col = (c & 3) * 16;
            cp16(sA + r * A_STRIDE_B + col, (const char*)(Ag + (size_t)r * K) + col);
            cp16(sB + r * A_STRIDE_B + col, (const char*)(Bg + (size_t)r * K) + col);
        }
        CP_COMMIT();
    }

    const uint32_t aOff = (wm + (lane & 15)) * A_STRIDE_B + (lane >> 4) * 16;
    const uint32_t bOff = (wn + (lane & 7)) * A_STRIDE_B + ((lane >> 3) & 1) * 16;

    for (int it = 0; it < nIter; ++it) {
        if (it + 1 < nIter) {
            int st = (it + 1) & 1;
            uint32_t sA = sbase + st * STAGE_B, sB = sA + GBM * A_STRIDE_B;
            int kt = (it + 1) << 5;
#pragma unroll
            for (int c = tid; c < 512; c += 256) {
                int r = c >> 2, col = (c & 3) * 16;
                cp16(sA + r * A_STRIDE_B + col, (const char*)(Ag + (size_t)r * K + kt) + col);
                cp16(sB + r * A_STRIDE_B + col, (const char*)(Bg + (size_t)r * K + kt) + col);
            }
            CP_COMMIT();
            asm volatile("cp.async.wait_group 1;" ::: "memory");
        } else {
            asm volatile("cp.async.wait_group 0;" ::: "memory");
        }
        __syncthreads();

        uint32_t sA = sbase + (it & 1) * STAGE_B + aOff;
        uint32_t sB = sbase + (it & 1) * STAGE_B + GBM * A_STRIDE_B + bOff;
#pragma unroll
        for (int ks = 0; ks < 2; ++ks) {
            uint32_t a[4][4], b[4][2];
#pragma unroll
            for (int mt = 0; mt < 4; ++mt)
                LDSM_X4(a[mt][0], a[mt][1], a[mt][2], a[mt][3],
                        sA + mt * (16 * A_STRIDE_B) + ks * 32);
#pragma unroll
            for (int nt = 0; nt < 4; ++nt)
                LDSM_X2(b[nt][0], b[nt][1], sB + nt * (8 * A_STRIDE_B) + ks * 32);
#pragma unroll
            for (int mt = 0; mt < 4; ++mt)
#pragma unroll
                for (int nt = 0; nt < 4; ++nt)
                    MMA16816(acc[mt][nt], a[mt], b[nt]);
        }
        __syncthreads();
    }

    // epilogue
    const int qr = lane >> 2, qc = (lane & 3) * 2;
#pragma unroll
    for (int mt = 0; mt < 4; ++mt) {
        int row = m0 + wm + mt * 16 + qr;
#pragma unroll
        for (int nt = 0; nt < 4; ++nt) {
            int col = n0 + wn + nt * 8 + qc;
            *(float2*)(C + (size_t)row * N + col) =
                make_float2(acc[mt][nt][0], acc[mt][nt][1]);
            *(float2*)(C + (size_t)(row + 8) * N + col) =
                make_float2(acc[mt][nt][2], acc[mt][nt][3]);
        }
    }
}

// =====================================================================
// fp32 [R,C] -> fp16 split-K A_ext [R,3C] = [Ah | Ah | Al]
// =====================================================================
__global__ void cvt_split(const float* __restrict__ A, __half* __restrict__ out,
                          int R, int C) {
    int i2 = (blockIdx.x * 256 + threadIdx.x) * 2;
    if (i2 >= R * C) return;
    int r = i2 / C, c = i2 - r * C;
    float2 v = *(const float2*)(A + i2);
    __half h0 = __float2half(v.x), h1 = __float2half(v.y);
    __half2 hh; hh.x = h0; hh.y = h1;
    __half2 ll;
    ll.x = __float2half(v.x - __half2float(h0));
    ll.y = __float2half(v.y - __half2float(h1));
    __half* row = out + (size_t)r * 3 * C;
    *(__half2*)(row + c) = hh;
    *(__half2*)(row + C + c) = hh;
    *(__half2*)(row + 2 * C + c) = ll;
}

// fp32 W[K,N] -> fp16 transposed split B_ext [N,3K] = [Bh | Bl | Bh]
__global__ void cvt_T_split(const float* __restrict__ W, __half* __restrict__ out,
                            int K, int N) {
    __shared__ float t[32][33];
    int k0 = blockIdx.y * 32, n0 = blockIdx.x * 32;
    int tx = threadIdx.x, ty = threadIdx.y;            // 32 x 8
#pragma unroll
    for (int j = 0; j < 32; j += 8)
        t[ty + j][tx] = W[(size_t)(k0 + ty + j) * N + n0 + tx];
    __syncthreads();
#pragma unroll
    for (int j = 0; j < 32; j += 8) {
        float a = t[tx][ty + j];                        // W[k0+tx][n0+ty+j]
        __half h = __float2half(a);
        __half l = __float2half(a - __half2float(h));
        size_t n = n0 + ty + j, k = k0 + tx;
        __half* row = out + n * (size_t)(3 * K);
        row[k] = h;
        row[K + k] = l;
        row[2 * K + k] = h;
    }
}

// =====================================================================
// causal depthwise conv (K=4) + SiLU
// =====================================================================
__global__ void conv_silu_kernel(const float* __restrict__ conv_w,
                                 const float* __restrict__ conv_b) {
    int idx = blockIdx.x * blockDim.x + threadIdx.x;
    if (idx >= L_SEQ * D_INNER) return;
    int d = idx & (D_INNER - 1);
    int t = idx >> 11;

    float w0 = conv_w[d * 4 + 0], w1 = conv_w[d * 4 + 1];
    float w2 = conv_w[d * 4 + 2], w3 = conv_w[d * 4 + 3];
    float s = conv_b[d];
    if (t >= 3) s += g_xr[(size_t)(t - 3) * 4096 + d] * w0;
    if (t >= 2) s += g_xr[(size_t)(t - 2) * 4096 + d] * w1;
    if (t >= 1) s += g_xr[(size_t)(t - 1) * 4096 + d] * w2;
    s += g_xr[(size_t)t * 4096 + d] * w3;
    float sig = 1.f / (1.f + __expf(-s));
    g_xconv[(size_t)t * D_INNER + d] = s * sig;
}

// =====================================================================
// x_dbl = x_conv @ W_x   [1024,96]  (8 t-rows per block share W_x reads)
// =====================================================================
__global__ void xdbl_kernel(const float* __restrict__ Wx) {
    __shared__ float xs[8][256];
    int t0 = blockIdx.x * 8;
    int n = threadIdx.x;                               // 0..95
    float acc[8];
#pragma unroll
    for (int tt = 0; tt < 8; ++tt) acc[tt] = 0.f;

    for (int k0 = 0; k0 < D_INNER; k0 += 256) {
        for (int i = n; i < 8 * 256; i += 96) {
            int tt = i >> 8, kk = i & 255;
            xs[tt][kk] = g_xconv[(size_t)(t0 + tt) * D_INNER + k0 + kk];
        }
        __syncthreads();
#pragma unroll 4
        for (int kk = 0; kk < 256; ++kk) {
            float w = Wx[(size_t)(k0 + kk) * X_DBL_W + n];
#pragma unroll
            for (int tt = 0; tt < 8; ++tt) acc[tt] = fmaf(xs[tt][kk], w, acc[tt]);
        }
        __syncthreads();
    }
#pragma unroll
    for (int tt = 0; tt < 8; ++tt) g_xdbl[(t0 + tt) * X_DBL_W + n] = acc[tt];
}

// =====================================================================
// delta = softplus(dt @ W_dt + b_dt)   (16 t-rows per block share W_dt)
// =====================================================================
__global__ void delta_kernel(const float* __restrict__ Wdt,
                             const float* __restrict__ bdt) {
    __shared__ float dts[16][64];
    int d = blockIdx.x * 256 + threadIdx.x;
    int t0 = blockIdx.y * 16;

    for (int i = threadIdx.x; i < 16 * 64; i += 256) {
        int tt = i >> 6, kk = i & 63;
        dts[tt][kk] = g_xdbl[(t0 + tt) * X_DBL_W + kk];
    }
    __syncthreads();

    float bb = bdt[d];
    float acc[16];
#pragma unroll
    for (int tt = 0; tt < 16; ++tt) acc[tt] = bb;
#pragma unroll 4
    for (int k = 0; k < DT_RANK; ++k) {
        float w = Wdt[(size_t)k * D_INNER + d];
#pragma unroll
        for (int tt = 0; tt < 16; ++tt) acc[tt] = fmaf(dts[tt][k], w, acc[tt]);
    }
#pragma unroll
    for (int tt = 0; tt < 16; ++tt) {
        float a = acc[tt];
        float sp = (a > 20.f) ? a : log1pf(__expf(a));
        g_delta[(size_t)(t0 + tt) * D_INNER + d] = sp;
    }
}

// =====================================================================
// selective scan + D skip + silu(res) gating
// =====================================================================
__global__ void scan_kernel(const float* __restrict__ A_log,
                            const float* __restrict__ Dp) {
    int tid = threadIdx.x;
    int g = tid >> 4;
    int n = tid & 15;
    int d = blockIdx.x * 8 + g;

    float Aval = -__expf(A_log[d * N_STATE + n]);
    float Dd = Dp[d];
    float h = 0.f;

    for (int t = 0; t < L_SEQ; ++t) {
        float dl = g_delta[(size_t)t * D_INNER + d];
        float u  = g_xconv[(size_t)t * D_INNER + d];
        float Bv = g_xdbl[t * X_DBL_W + DT_RANK + n];
        float Cv = g_xdbl[t * X_DBL_W + DT_RANK + N_STATE + n];

        float dA = __expf(dl * Aval);
        h = fmaf(dA, h, dl * Bv * u);
        float part = h * Cv;
        part += __shfl_xor_sync(0xffffffffu, part, 8, 16);
        part += __shfl_xor_sync(0xffffffffu, part, 4, 16);
        part += __shfl_xor_sync(0xffffffffu, part, 2, 16);
        part += __shfl_xor_sync(0xffffffffu, part, 1, 16);

        if (n == 0) {
            float r = g_xr[(size_t)t * 4096 + D_INNER + d];
            float sr = r / (1.f + __expf(-r));
            g_ysc[(size_t)t * D_INNER + d] = (part + u * Dd) * sr;
        }
    }
}

// =====================================================================
// launch
// =====================================================================
template <typename T>
static T* sym_addr(const void* sym) {
    void* p = nullptr;
    cudaGetSymbolAddress(&p, sym);
    return (T*)p;
}

extern "C" void kernel_launch(void* const* d_in, const int* in_sizes, int n_in,
                              void* d_out, int out_size) {
    const float* x      = (const float*)d_in[0];
    const float* W_in   = (const float*)d_in[1];
    const float* conv_w = (const float*)d_in[2];
    const float* conv_b = (const float*)d_in[3];
    const float* W_x    = (const float*)d_in[4];
    const float* W_dt   = (const float*)d_in[5];
    const float* b_dt   = (const float*)d_in[6];
    const float* A_log  = (const float*)d_in[7];
    const float* Dvec   = (const float*)d_in[8];
    const float* W_out  = (const float*)d_in[9];
    float* out = (float*)d_out;

    float* xr   = sym_addr<float>(g_xr);
    float* ysc  = sym_addr<float>(g_ysc);
    __half* ae  = sym_addr<__half>(g_aext);
    __half* b1e = sym_addr<__half>(g_b1e);
    __half* b2e = sym_addr<__half>(g_b2e);

    // --- conversions ---
    cvt_split<<<(1024 * 1024 / 2 + 255) / 256, 256>>>(x, ae, 1024, 1024);
    cvt_T_split<<<dim3(4096 / 32, 1024 / 32), dim3(32, 8)>>>(W_in, b1e, 1024, 4096);
    cvt_T_split<<<dim3(1024 / 32, 2048 / 32), dim3(32, 8)>>>(W_out, b2e, 2048, 1024);

    // 1) x_and_res = x @ W_in    [1024,4096], K'=3072
    gemm_mma<<<dim3(4096 / GBN, 1024 / GBM), 256>>>(ae, b1e, xr, 1024, 4096, 3072);

    // 2) conv + silu
    conv_silu_kernel<<<(L_SEQ * D_INNER + 255) / 256, 256>>>(conv_w, conv_b);

    // 3) x_dbl
    xdbl_kernel<<<L_SEQ / 8, X_DBL_W>>>(W_x);

    // 4) delta
    delta_kernel<<<dim3(D_INNER / 256, L_SEQ / 16), 256>>>(W_dt, b_dt);

    // 5) selective scan
    scan_kernel<<<D_INNER / 8, 128>>>(A_log, Dvec);

    // 6) out = ysc @ W_out   [1024,1024], K'=6144
    cvt_split<<<(1024 * 2048 / 2 + 255) / 256, 256>>>(ysc, ae, 1024, 2048);
    gemm_mma<<<dim3(1024 / GBN, 1024 / GBM), 256>>>(ae, b2e, out, 1024, 1024, 6144);
}

// round 11
// speedup vs baseline: 2.3072x; 2.0231x over previous
#include <cuda_runtime.h>
#include <cuda_fp16.h>
#include <cstdint>

// ---------------- problem constants ----------------
#define L_SEQ    1024
#define D_MODEL  1024
#define D_INNER  2048
#define N_STATE  16
#define DT_RANK  64
#define X_DBL_W  96   // DT_RANK + 2*N_STATE
#define CHUNK    32
#define NCHUNK   (L_SEQ / CHUNK)   // 32

// ---------------- fp32 scratch ----------------
__device__ float g_xr[L_SEQ * 2 * D_INNER];      // x_and_res [1024,4096]
__device__ float g_xconv[L_SEQ * D_INNER];       // [1024,2048]
__device__ float g_xdbl[L_SEQ * X_DBL_W];        // [1024,96]
__device__ float g_delta[L_SEQ * D_INNER];       // [1024,2048]
__device__ float g_ysc[L_SEQ * D_INNER];         // (y+u*D)*silu(res)
__device__ float g_tmp[1024 * 1024];             // GEMM2 split-K partial

// ---------------- chunked-scan scratch ----------------
__device__ float g_P[NCHUNK * D_INNER * N_STATE];   // chunk decay product
__device__ float g_S[NCHUNK * D_INNER * N_STATE];   // chunk local end-state
__device__ float g_h0[NCHUNK * D_INNER * N_STATE];  // chunk start-state

// ---------------- fp16 split-K scratch ----------------
// A_ext = [Ah | Ah | Al]  (M x 3K), B_ext = [Bh | Bl | Bh]  (N x 3K)
__device__ __half g_aext[1024 * 6144];           // max: ysc split (1024 x 3*2048)
__device__ __half g_b1e[4096 * 3072];            // W_in^T split
__device__ __half g_b2e[1024 * 6144];            // W_out^T split

// =====================================================================
// base-PTX helpers (compute_103-safe: ldmatrix / mma.sync / cp.async)
// =====================================================================
__device__ __forceinline__ uint32_t smem_u32(const void* p) {
    uint32_t a;
    asm("{ .reg .u64 t; cvta.to.shared.u64 t, %1; cvt.u32.u64 %0, t; }" : "=r"(a) : "l"(p));
    return a;
}
__device__ __forceinline__ void cp16(uint32_t s, const void* g) {
    asm volatile("cp.async.cg.shared.global [%0], [%1], 16;" :: "r"(s), "l"(g));
}
#define CP_COMMIT() asm volatile("cp.async.commit_group;" ::: "memory")

#define LDSM_X4(r0, r1, r2, r3, addr) \
    asm volatile("ldmatrix.sync.aligned.m8n8.x4.shared.b16 {%0,%1,%2,%3}, [%4];" \
        : "=r"(r0), "=r"(r1), "=r"(r2), "=r"(r3) : "r"(addr))
#define LDSM_X2(r0, r1, addr) \
    asm volatile("ldmatrix.sync.aligned.m8n8.x2.shared.b16 {%0,%1}, [%2];" \
        : "=r"(r0), "=r"(r1) : "r"(addr))
#define MMA16816(d, a, b) \
    asm volatile("mma.sync.aligned.m16n8k16.row.col.f32.f16.f16.f32 " \
        "{%0,%1,%2,%3}, {%4,%5,%6,%7}, {%8,%9}, {%0,%1,%2,%3};" \
        : "+f"((d)[0]), "+f"((d)[1]), "+f"((d)[2]), "+f"((d)[3]) \
        : "r"((a)[0]), "r"((a)[1]), "r"((a)[2]), "r"((a)[3]), "r"((b)[0]), "r"((b)[1]))

// =====================================================================
// HMMA GEMM: C[M,N] = A[M,K] @ B[N,K]^T, fp16 in, fp32 out
// tile 128x128x32, 8 warps, cp.async double buffer
// lda = element stride of A/B rows. Optional K-split over gridDim.z:
// z==1 CTAs compute columns [ksplit, ksplit+K) into C2.
// =====================================================================
#define GBM 128
#define GBN 128
#define A_STRIDE_B 80              // bytes per smem row (32 halves + 8 pad)
#define STAGE_B (GBM * A_STRIDE_B + GBN * A_STRIDE_B)   // 20480

__global__ void __launch_bounds__(256, 2) gemm_mma(
    const __half* __restrict__ A, const __half* __restrict__ B,
    float* __restrict__ C, int M, int N, int K, int lda,
    float* __restrict__ C2, int ksplit) {
    __shared__ __align__(16) char smem[2 * STAGE_B];
    const uint32_t sbase = smem_u32(smem);
    const int tid = threadIdx.x;
    const int lane = tid & 31, wid = tid >> 5;
    const int m0 = blockIdx.y * GBM, n0 = blockIdx.x * GBN;

    if (blockIdx.z == 1) { A += ksplit; B += ksplit; C = C2; }

    const __half* Ag = A + (size_t)m0 * lda;
    const __half* Bg = B + (size_t)n0 * lda;

    const int wm = (wid & 1) * 64;
    const int wn = (wid >> 1) * 32;

    float acc[4][4][4];
#pragma unroll
    for (int i = 0; i < 4; ++i)
#pragma unroll
        for (int j = 0; j < 4; ++j)
#pragma unroll
            for (int q = 0; q < 4; ++q) acc[i][j][q] = 0.f;

    const int nIter = K >> 5;

    // prefetch tile 0
    {
        uint32_t sA = sbase, sB = sbase + GBM * A_STRIDE_B;
#pragma unroll
        for (int c = tid; c < 512; c += 256) {
            int r = c >> 2, col = (c & 3) * 16;
            cp16(sA + r * A_STRIDE_B + col, (const char*)(Ag + (size_t)r * lda) + col);
            cp16(sB + r * A_STRIDE_B + col, (const char*)(Bg + (size_t)r * lda) + col);
        }
        CP_COMMIT();
    }

    const uint32_t aOff = (wm + (lane & 15)) * A_STRIDE_B + (lane >> 4) * 16;
    const uint32_t bOff = (wn + (lane & 7)) * A_STRIDE_B + ((lane >> 3) & 1) * 16;

    for (int it = 0; it < nIter; ++it) {
        if (it + 1 < nIter) {
            int st = (it + 1) & 1;
            uint32_t sA = sbase + st * STAGE_B, sB = sA + GBM * A_STRIDE_B;
            int kt = (it + 1) << 5;
#pragma unroll
            for (int c = tid; c < 512; c += 256) {
                int r = c >> 2, col = (c & 3) * 16;
                cp16(sA + r * A_STRIDE_B + col, (const char*)(Ag + (size_t)r * lda + kt) + col);
                cp16(sB + r * A_STRIDE_B + col, (const char*)(Bg + (size_t)r * lda + kt) + col);
            }
            CP_COMMIT();
            asm volatile("cp.async.wait_group 1;" ::: "memory");
        } else {
            asm volatile("cp.async.wait_group 0;" ::: "memory");
        }
        __syncthreads();

        uint32_t sA = sbase + (it & 1) * STAGE_B + aOff;
        uint32_t sB = sbase + (it & 1) * STAGE_B + GBM * A_STRIDE_B + bOff;
#pragma unroll
        for (int ks = 0; ks < 2; ++ks) {
            uint32_t a[4][4], b[4][2];
#pragma unroll
            for (int mt = 0; mt < 4; ++mt)
                LDSM_X4(a[mt][0], a[mt][1], a[mt][2], a[mt][3],
                        sA + mt * (16 * A_STRIDE_B) + ks * 32);
#pragma unroll
            for (int nt = 0; nt < 4; ++nt)
                LDSM_X2(b[nt][0], b[nt][1], sB + nt * (8 * A_STRIDE_B) + ks * 32);
#pragma unroll
            for (int mt = 0; mt < 4; ++mt)
#pragma unroll
                for (int nt = 0; nt < 4; ++nt)
                    MMA16816(acc[mt][nt], a[mt], b[nt]);
        }
        __syncthreads();
    }

    // epilogue
    const int qr = lane >> 2, qc = (lane & 3) * 2;
#pragma unroll
    for (int mt = 0; mt < 4; ++mt) {
        int row = m0 + wm + mt * 16 + qr;
#pragma unroll
        for (int nt = 0; nt < 4; ++nt) {
            int col = n0 + wn + nt * 8 + qc;
            *(float2*)(C + (size_t)row * N + col) =
                make_float2(acc[mt][nt][0], acc[mt][nt][1]);
            *(float2*)(C + (size_t)(row + 8) * N + col) =
                make_float2(acc[mt][nt][2], acc[mt][nt][3]);
        }
    }
}

// out += tmp   (GEMM2 split-K reduction)
__global__ void add_kernel(float* __restrict__ out, const float* __restrict__ tmp) {
    int i = (blockIdx.x * 256 + threadIdx.x) * 4;
    float4 a = *(const float4*)(out + i);
    float4 b = *(const float4*)(tmp + i);
    a.x += b.x; a.y += b.y; a.z += b.z; a.w += b.w;
    *(float4*)(out + i) = a;
}

// =====================================================================
// fp32 [R,C] -> fp16 split-K A_ext [R,3C] = [Ah | Ah | Al]
// =====================================================================
__global__ void cvt_split(const float* __restrict__ A, __half* __restrict__ out,
                          int R, int C) {
    int i2 = (blockIdx.x * 256 + threadIdx.x) * 2;
    if (i2 >= R * C) return;
    int r = i2 / C, c = i2 - r * C;
    float2 v = *(const float2*)(A + i2);
    __half h0 = __float2half(v.x), h1 = __float2half(v.y);
    __half2 hh; hh.x = h0; hh.y = h1;
    __half2 ll;
    ll.x = __float2half(v.x - __half2float(h0));
    ll.y = __float2half(v.y - __half2float(h1));
    __half* row = out + (size_t)r * 3 * C;
    *(__half2*)(row + c) = hh;
    *(__half2*)(row + C + c) = hh;
    *(__half2*)(row + 2 * C + c) = ll;
}

// fp32 W[K,N] -> fp16 transposed split B_ext [N,3K] = [Bh | Bl | Bh]
__global__ void cvt_T_split(const float* __restrict__ W, __half* __restrict__ out,
                            int K, int N) {
    __shared__ float t[32][33];
    int k0 = blockIdx.y * 32, n0 = blockIdx.x * 32;
    int tx = threadIdx.x, ty = threadIdx.y;            // 32 x 8
#pragma unroll
    for (int j = 0; j < 32; j += 8)
        t[ty + j][tx] = W[(size_t)(k0 + ty + j) * N + n0 + tx];
    __syncthreads();
#pragma unroll
    for (int j = 0; j < 32; j += 8) {
        float a = t[tx][ty + j];                        // W[k0+tx][n0+ty+j]
        __half h = __float2half(a);
        __half l = __float2half(a - __half2float(h));
        size_t n = n0 + ty + j, k = k0 + tx;
        __half* row = out + n * (size_t)(3 * K);
        row[k] = h;
        row[K + k] = l;
        row[2 * K + k] = h;
    }
}

// =====================================================================
// causal depthwise conv (K=4) + SiLU
// =====================================================================
__global__ void conv_silu_kernel(const float* __restrict__ conv_w,
                                 const float* __restrict__ conv_b) {
    int idx = blockIdx.x * blockDim.x + threadIdx.x;
    if (idx >= L_SEQ * D_INNER) return;
    int d = idx & (D_INNER - 1);
    int t = idx >> 11;

    float w0 = conv_w[d * 4 + 0], w1 = conv_w[d * 4 + 1];
    float w2 = conv_w[d * 4 + 2], w3 = conv_w[d * 4 + 3];
    float s = conv_b[d];
    if (t >= 3) s += g_xr[(size_t)(t - 3) * 4096 + d] * w0;
    if (t >= 2) s += g_xr[(size_t)(t - 2) * 4096 + d] * w1;
    if (t >= 1) s += g_xr[(size_t)(t - 1) * 4096 + d] * w2;
    s += g_xr[(size_t)t * 4096 + d] * w3;
    g_xconv[(size_t)t * D_INNER + d] = __fdividef(s, 1.f + __expf(-s));
}

// =====================================================================
// x_dbl = x_conv @ W_x   [1024,96]  (8 t-rows per block share W_x reads)
// =====================================================================
__global__ void xdbl_kernel(const float* __restrict__ Wx) {
    __shared__ float xs[8][256];
    int t0 = blockIdx.x * 8;
    int n = threadIdx.x;                               // 0..95
    float acc[8];
#pragma unroll
    for (int tt = 0; tt < 8; ++tt) acc[tt] = 0.f;

    for (int k0 = 0; k0 < D_INNER; k0 += 256) {
        for (int i = n; i < 8 * 256; i += 96) {
            int tt = i >> 8, kk = i & 255;
            xs[tt][kk] = g_xconv[(size_t)(t0 + tt) * D_INNER + k0 + kk];
        }
        __syncthreads();
#pragma unroll 4
        for (int kk = 0; kk < 256; ++kk) {
            float w = Wx[(size_t)(k0 + kk) * X_DBL_W + n];
#pragma unroll
            for (int tt = 0; tt < 8; ++tt) acc[tt] = fmaf(xs[tt][kk], w, acc[tt]);
        }
        __syncthreads();
    }
#pragma unroll
    for (int tt = 0; tt < 8; ++tt) g_xdbl[(t0 + tt) * X_DBL_W + n] = acc[tt];
}

// =====================================================================
// delta = softplus(dt @ W_dt + b_dt)   (16 t-rows per block share W_dt)
// =====================================================================
__global__ void delta_kernel(const float* __restrict__ Wdt,
                             const float* __restrict__ bdt) {
    __shared__ float dts[16][64];
    int d = blockIdx.x * 256 + threadIdx.x;
    int t0 = blockIdx.y * 16;

    for (int i = threadIdx.x; i < 16 * 64; i += 256) {
        int tt = i >> 6, kk = i & 63;
        dts[tt][kk] = g_xdbl[(t0 + tt) * X_DBL_W + kk];
    }
    __syncthreads();

    float bb = bdt[d];
    float acc[16];
#pragma unroll
    for (int tt = 0; tt < 16; ++tt) acc[tt] = bb;
#pragma unroll 4
    for (int k = 0; k < DT_RANK; ++k) {
        float w = Wdt[(size_t)k * D_INNER + d];
#pragma unroll
        for (int tt = 0; tt < 16; ++tt) acc[tt] = fmaf(dts[tt][k], w, acc[tt]);
    }
#pragma unroll
    for (int tt = 0; tt < 16; ++tt) {
        float a = acc[tt];
        float sp = (a > 20.f) ? a : log1pf(__expf(a));
        g_delta[(size_t)(t0 + tt) * D_INNER + d] = sp;
    }
}

// =====================================================================
// chunked selective scan
//   h_t = dA_t * h_{t-1} + dBu_t  is affine in h -> chunk-composable.
// P1: per chunk, P = prod(dA), S = local end state (h0 = 0)
// P2: propagate h0 across the 32 chunk summaries (sequential, tiny)
// P3: re-run chunk from true h0, emit gated outputs
// =====================================================================
__global__ void scan_p1(const float* __restrict__ A_log) {
    int tid = threadIdx.x;               // 128
    int g = tid >> 4, n = tid & 15;
    int d = blockIdx.x * 8 + g;
    int c = blockIdx.y;

    float Aval = -__expf(A_log[d * N_STATE + n]);
    float P = 1.f, S = 0.f;
    int tbase = c * CHUNK;
#pragma unroll 8
    for (int i = 0; i < CHUNK; ++i) {
        int t = tbase + i;
        float dl = g_delta[(size_t)t * D_INNER + d];
        float u  = g_xconv[(size_t)t * D_INNER + d];
        float Bv = g_xdbl[t * X_DBL_W + DT_RANK + n];
        float dA = __expf(dl * Aval);
        S = fmaf(dA, S, dl * Bv * u);
        P *= dA;
    }
    int idx = (c * D_INNER + d) * N_STATE + n;
    g_P[idx] = P;
    g_S[idx] = S;
}

__global__ void scan_p2() {
    int dn = blockIdx.x * 256 + threadIdx.x;   // 0 .. 32767 (d*16+n)
    float h = 0.f;
#pragma unroll
    for (int c = 0; c < NCHUNK; ++c) {
        int idx = c * (D_INNER * N_STATE) + dn;
        g_h0[idx] = h;
        h = fmaf(g_P[idx], h, g_S[idx]);
    }
}

__global__ void scan_p3(const float* __restrict__ A_log,
                        const float* __restrict__ Dp) {
    int tid = threadIdx.x;               // 128
    int g = tid >> 4, n = tid & 15;
    int d = blockIdx.x * 8 + g;
    int c = blockIdx.y;

    float Aval = -__expf(A_log[d * N_STATE + n]);
    float Dd = Dp[d];
    float h = g_h0[(c * D_INNER + d) * N_STATE + n];
    int tbase = c * CHUNK;
#pragma unroll 4
    for (int i = 0; i < CHUNK; ++i) {
        int t = tbase + i;
        float dl = g_delta[(size_t)t * D_INNER + d];
        float u  = g_xconv[(size_t)t * D_INNER + d];
        float Bv = g_xdbl[t * X_DBL_W + DT_RANK + n];
        float Cv = g_xdbl[t * X_DBL_W + DT_RANK + N_STATE + n];

        float dA = __expf(dl * Aval);
        h = fmaf(dA, h, dl * Bv * u);
        float part = h * Cv;
        part += __shfl_xor_sync(0xffffffffu, part, 8, 16);
        part += __shfl_xor_sync(0xffffffffu, part, 4, 16);
        part += __shfl_xor_sync(0xffffffffu, part, 2, 16);
        part += __shfl_xor_sync(0xffffffffu, part, 1, 16);

        if (n == 0) {
            float r = g_xr[(size_t)t * 4096 + D_INNER + d];
            float sr = __fdividef(r, 1.f + __expf(-r));
            g_ysc[(size_t)t * D_INNER + d] = (part + u * Dd) * sr;
        }
    }
}

// =====================================================================
// launch
// =====================================================================
template <typename T>
static T* sym_addr(const void* sym) {
    void* p = nullptr;
    cudaGetSymbolAddress(&p, sym);
    return (T*)p;
}

extern "C" void kernel_launch(void* const* d_in, const int* in_sizes, int n_in,
                              void* d_out, int out_size) {
    const float* x      = (const float*)d_in[0];
    const float* W_in   = (const float*)d_in[1];
    const float* conv_w = (const float*)d_in[2];
    const float* conv_b = (const float*)d_in[3];
    const float* W_x    = (const float*)d_in[4];
    const float* W_dt   = (const float*)d_in[5];
    const float* b_dt   = (const float*)d_in[6];
    const float* A_log  = (const float*)d_in[7];
    const float* Dvec   = (const float*)d_in[8];
    const float* W_out  = (const float*)d_in[9];
    float* out = (float*)d_out;

    float* xr   = sym_addr<float>(g_xr);
    float* ysc  = sym_addr<float>(g_ysc);
    float* tmp  = sym_addr<float>(g_tmp);
    __half* ae  = sym_addr<__half>(g_aext);
    __half* b1e = sym_addr<__half>(g_b1e);
    __half* b2e = sym_addr<__half>(g_b2e);

    // --- conversions ---
    cvt_split<<<(1024 * 1024 / 2 + 255) / 256, 256>>>(x, ae, 1024, 1024);
    cvt_T_split<<<dim3(4096 / 32, 1024 / 32), dim3(32, 8)>>>(W_in, b1e, 1024, 4096);
    cvt_T_split<<<dim3(1024 / 32, 2048 / 32), dim3(32, 8)>>>(W_out, b2e, 2048, 1024);

    // 1) x_and_res = x @ W_in    [1024,4096], K'=3072
    gemm_mma<<<dim3(4096 / GBN, 1024 / GBM, 1), 256>>>(ae, b1e, xr, 1024, 4096, 3072,
                                                       3072, nullptr, 0);

    // 2) conv + silu
    conv_silu_kernel<<<(L_SEQ * D_INNER + 255) / 256, 256>>>(conv_w, conv_b);

    // 3) x_dbl
    xdbl_kernel<<<L_SEQ / 8, X_DBL_W>>>(W_x);

    // 4) delta
    delta_kernel<<<dim3(D_INNER / 256, L_SEQ / 16), 256>>>(W_dt, b_dt);

    // 5) chunked selective scan
    scan_p1<<<dim3(D_INNER / 8, NCHUNK), 128>>>(A_log);
    scan_p2<<<D_INNER * N_STATE / 256, 256>>>();
    scan_p3<<<dim3(D_INNER / 8, NCHUNK), 128>>>(A_log, Dvec);

    // 6) out = ysc @ W_out  [1024,1024], K'=6144, split-K over gridDim.z
    cvt_split<<<(1024 * 2048 / 2 + 255) / 256, 256>>>(ysc, ae, 1024, 2048);
    gemm_mma<<<dim3(1024 / GBN, 1024 / GBM, 2), 256>>>(ae, b2e, out, 1024, 1024, 3072,
                                                       6144, tmp, 3072);
    add_kernel<<<1024 * 1024 / 1024, 256>>>(out, tmp);
}

// round 12
// speedup vs baseline: 3.4870x; 1.5114x over previous
#include <cuda_runtime.h>
#include <cuda_fp16.h>
#include <cstdint>

// ---------------- problem constants ----------------
#define L_SEQ    1024
#define D_MODEL  1024
#define D_INNER  2048
#define N_STATE  16
#define DT_RANK  64
#define X_DBL_W  96   // DT_RANK + 2*N_STATE
#define CHUNK    32
#define NCHUNK   (L_SEQ / CHUNK)   // 32

// ---------------- fp32 scratch ----------------
__device__ float g_xr[L_SEQ * 2 * D_INNER];      // x_and_res [1024,4096]
__device__ float g_xconv[L_SEQ * D_INNER];       // [1024,2048]
__device__ float g_xdbl[L_SEQ * X_DBL_W];        // [1024,96]
__device__ float g_xdp[4 * L_SEQ * X_DBL_W];     // xdbl K-split partials
__device__ float g_delta[L_SEQ * D_INNER];       // [1024,2048]
__device__ float g_ysc[L_SEQ * D_INNER];         // (y+u*D)*silu(res)
__device__ float g_tmp[3 * 1024 * 1024];         // GEMM2 split-K partials

// ---------------- chunked-scan scratch ----------------
__device__ float g_P[NCHUNK * D_INNER * N_STATE];
__device__ float g_S[NCHUNK * D_INNER * N_STATE];
__device__ float g_h0[NCHUNK * D_INNER * N_STATE];

// ---------------- fp16 split scratch ----------------
// A = [Ah | Al] (M x 2K) row-major; B = [Bh ; Bl ; Bh] (3K x N) K-major
__device__ __half g_aext[1024 * 4096];           // max: ysc split (1024 x 2*2048)
__device__ __half g_b1e[3072 * 4096];            // W_in split  [3*1024, 4096]
__device__ __half g_b2e[6144 * 1024];            // W_out split [3*2048, 1024]

// =====================================================================
// base-PTX helpers (compute_103-safe)
// =====================================================================
__device__ __forceinline__ uint32_t smem_u32(const void* p) {
    uint32_t a;
    asm("{ .reg .u64 t; cvta.to.shared.u64 t, %1; cvt.u32.u64 %0, t; }" : "=r"(a) : "l"(p));
    return a;
}
__device__ __forceinline__ void cp16(uint32_t s, const void* g) {
    asm volatile("cp.async.cg.shared.global [%0], [%1], 16;" :: "r"(s), "l"(g));
}
#define CP_COMMIT() asm volatile("cp.async.commit_group;" ::: "memory")

#define LDSM_X4(r0, r1, r2, r3, addr) \
    asm volatile("ldmatrix.sync.aligned.m8n8.x4.shared.b16 {%0,%1,%2,%3}, [%4];" \
        : "=r"(r0), "=r"(r1), "=r"(r2), "=r"(r3) : "r"(addr))
#define LDSM_X2_T(r0, r1, addr) \
    asm volatile("ldmatrix.sync.aligned.m8n8.x2.trans.shared.b16 {%0,%1}, [%2];" \
        : "=r"(r0), "=r"(r1) : "r"(addr))
#define MMA16816(d, a, b) \
    asm volatile("mma.sync.aligned.m16n8k16.row.col.f32.f16.f16.f32 " \
        "{%0,%1,%2,%3}, {%4,%5,%6,%7}, {%8,%9}, {%0,%1,%2,%3};" \
        : "+f"((d)[0]), "+f"((d)[1]), "+f"((d)[2]), "+f"((d)[3]) \
        : "r"((a)[0]), "r"((a)[1]), "r"((a)[2]), "r"((a)[3]), "r"((b)[0]), "r"((b)[1]))

// =====================================================================
// HMMA GEMM: C[M,N] = A[M,2K]@map x B[3K,N]
//   extended k: ke<K -> Ah*Bh, K<=ke<2K -> Ah*Bl, 2K<=ke -> Al*Bh
//   A col index = ke < korig ? ke : ke - korig     (A stores [Ah|Al])
// A row-major (lda), B K-major row-major (ldb = N stride).
// tile 128x128x32, 8 warps; B loaded via ldmatrix.trans.
// Optional split-K over gridDim.z -> C0..C3.
// =====================================================================
#define GBM 128
#define GBN 128
#define A_STR 80                   // 32 halves + 8 pad
#define B_STR 272                  // 128 halves + 8 pad
#define A_BYTES (128 * A_STR)      // 10240
#define B_BYTES (32 * B_STR)       // 8704
#define STAGE_B (A_BYTES + B_BYTES)

__global__ void __launch_bounds__(256, 2) gemm_mma(
    const __half* __restrict__ A, const __half* __restrict__ B,
    float* __restrict__ C0, float* __restrict__ C1,
    float* __restrict__ C2, float* __restrict__ C3,
    int N, int Kext, int korig, int lda, int ldb) {
    __shared__ __align__(16) char smem[2 * STAGE_B];
    const uint32_t sbase = smem_u32(smem);
    const int tid = threadIdx.x;
    const int lane = tid & 31, wid = tid >> 5;
    const int m0 = blockIdx.y * GBM, n0 = blockIdx.x * GBN;
    const int z = blockIdx.z;
    const int Kz = Kext / gridDim.z;
    const int ke0 = z * Kz;
    float* C = (z == 0) ? C0 : (z == 1) ? C1 : (z == 2) ? C2 : C3;

    const __half* Ag = A + (size_t)m0 * lda;
    const __half* Bg = B + n0;

    const int wm = (wid & 1) * 64;
    const int wn = (wid >> 1) * 32;

    float acc[4][4][4];
#pragma unroll
    for (int i = 0; i < 4; ++i)
#pragma unroll
        for (int j = 0; j < 4; ++j)
#pragma unroll
            for (int q = 0; q < 4; ++q) acc[i][j][q] = 0.f;

    const int nIter = Kz >> 5;

    // tile loader: A 128x32 (4 cp16/row-chunks), B 32x128 (16 cp16/row)
    auto load_tile = [&](int it, int stage) {
        int kt = ke0 + (it << 5);
        int kA = (kt < korig) ? kt : kt - korig;
        uint32_t sA = sbase + stage * STAGE_B;
        uint32_t sB = sA + A_BYTES;
#pragma unroll
        for (int c = tid; c < 1024; c += 256) {
            if (c < 512) {
                int r = c >> 2, col = (c & 3) * 16;
                cp16(sA + r * A_STR + col,
                     (const char*)(Ag + (size_t)r * lda + kA) + col);
            } else {
                int cc = c - 512;
                int r = cc >> 4, col = (cc & 15) * 16;
                cp16(sB + r * B_STR + col,
                     (const char*)(Bg + (size_t)(kt + r) * ldb) + col);
            }
        }
    };

    load_tile(0, 0);
    CP_COMMIT();

    const uint32_t aOff = (wm + (lane & 15)) * A_STR + (lane >> 4) * 16;
    const uint32_t bOff = (lane & 15) * B_STR + wn * 2;

    for (int it = 0; it < nIter; ++it) {
        if (it + 1 < nIter) {
            load_tile(it + 1, (it + 1) & 1);
            CP_COMMIT();
            asm volatile("cp.async.wait_group 1;" ::: "memory");
        } else {
            asm volatile("cp.async.wait_group 0;" ::: "memory");
        }
        __syncthreads();

        uint32_t sA = sbase + (it & 1) * STAGE_B + aOff;
        uint32_t sB = sbase + (it & 1) * STAGE_B + A_BYTES + bOff;
#pragma unroll
        for (int ks = 0; ks < 2; ++ks) {
            uint32_t a[4][4], b[4][2];
#pragma unroll
            for (int mt = 0; mt < 4; ++mt)
                LDSM_X4(a[mt][0], a[mt][1], a[mt][2], a[mt][3],
                        sA + mt * (16 * A_STR) + ks * 32);
#pragma unroll
            for (int nt = 0; nt < 4; ++nt)
                LDSM_X2_T(b[nt][0], b[nt][1], sB + ks * (16 * B_STR) + nt * 16);
#pragma unroll
            for (int mt = 0; mt < 4; ++mt)
#pragma unroll
                for (int nt = 0; nt < 4; ++nt)
                    MMA16816(acc[mt][nt], a[mt], b[nt]);
        }
        __syncthreads();
    }

    const int qr = lane >> 2, qc = (lane & 3) * 2;
#pragma unroll
    for (int mt = 0; mt < 4; ++mt) {
        int row = m0 + wm + mt * 16 + qr;
#pragma unroll
        for (int nt = 0; nt < 4; ++nt) {
            int col = n0 + wn + nt * 8 + qc;
            *(float2*)(C + (size_t)row * N + col) =
                make_float2(acc[mt][nt][0], acc[mt][nt][1]);
            *(float2*)(C + (size_t)(row + 8) * N + col) =
                make_float2(acc[mt][nt][2], acc[mt][nt][3]);
        }
    }
}

// out += t0 + t1 + t2   (GEMM2 split-K reduction, 1024x1024)
__global__ void add4_kernel(float* __restrict__ out) {
    int i = (blockIdx.x * 256 + threadIdx.x) * 4;
    float4 a = *(const float4*)(out + i);
    float4 b = *(const float4*)(g_tmp + i);
    float4 c = *(const float4*)(g_tmp + 1024 * 1024 + i);
    float4 d = *(const float4*)(g_tmp + 2 * 1024 * 1024 + i);
    a.x += b.x + c.x + d.x; a.y += b.y + c.y + d.y;
    a.z += b.z + c.z + d.z; a.w += b.w + c.w + d.w;
    *(float4*)(out + i) = a;
}

// =====================================================================
// fp32 [R,C] -> fp16 A-split [R,2C] = [Ah | Al]
// =====================================================================
__global__ void cvt_split(const float* __restrict__ A, __half* __restrict__ out,
                          int R, int C) {
    int i2 = (blockIdx.x * 256 + threadIdx.x) * 2;
    if (i2 >= R * C) return;
    int r = i2 / C, c = i2 - r * C;
    float2 v = *(const float2*)(A + i2);
    __half h0 = __float2half(v.x), h1 = __float2half(v.y);
    __half2 hh; hh.x = h0; hh.y = h1;
    __half2 ll;
    ll.x = __float2half(v.x - __half2float(h0));
    ll.y = __float2half(v.y - __half2float(h1));
    __half* row = out + (size_t)r * 2 * C;
    *(__half2*)(row + c) = hh;
    *(__half2*)(row + C + c) = ll;
}

// fp32 W[K,N] -> fp16 B-split [3K,N] = [Bh ; Bl ; Bh], coalesced half2
__global__ void cvt_Bsplit(const float* __restrict__ W, __half* __restrict__ out,
                           int KN) {
    int i2 = (blockIdx.x * 256 + threadIdx.x) * 2;
    if (i2 >= KN) return;
    float2 v = *(const float2*)(W + i2);
    __half h0 = __float2half(v.x), h1 = __float2half(v.y);
    __half2 hh; hh.x = h0; hh.y = h1;
    __half2 ll;
    ll.x = __float2half(v.x - __half2float(h0));
    ll.y = __float2half(v.y - __half2float(h1));
    *(__half2*)(out + i2) = hh;
    *(__half2*)(out + KN + i2) = ll;
    *(__half2*)(out + 2 * KN + i2) = hh;
}

// =====================================================================
// causal depthwise conv (K=4) + SiLU
// =====================================================================
__global__ void conv_silu_kernel(const float* __restrict__ conv_w,
                                 const float* __restrict__ conv_b) {
    int idx = blockIdx.x * blockDim.x + threadIdx.x;
    if (idx >= L_SEQ * D_INNER) return;
    int d = idx & (D_INNER - 1);
    int t = idx >> 11;

    float w0 = conv_w[d * 4 + 0], w1 = conv_w[d * 4 + 1];
    float w2 = conv_w[d * 4 + 2], w3 = conv_w[d * 4 + 3];
    float s = conv_b[d];
    if (t >= 3) s += g_xr[(size_t)(t - 3) * 4096 + d] * w0;
    if (t >= 2) s += g_xr[(size_t)(t - 2) * 4096 + d] * w1;
    if (t >= 1) s += g_xr[(size_t)(t - 1) * 4096 + d] * w2;
    s += g_xr[(size_t)t * 4096 + d] * w3;
    g_xconv[(size_t)t * D_INNER + d] = __fdividef(s, 1.f + __expf(-s));
}

// =====================================================================
// x_dbl = x_conv @ W_x  — K-split x4 over gridDim.y, partials + reduce
// =====================================================================
__global__ void xdbl_kernel(const float* __restrict__ Wx) {
    __shared__ float xs[8][256];
    int t0 = blockIdx.x * 8;
    int ks = blockIdx.y;                               // 0..3, K range 512
    int n = threadIdx.x;                               // 0..95
    float acc[8];
#pragma unroll
    for (int tt = 0; tt < 8; ++tt) acc[tt] = 0.f;

    int kbeg = ks * 512;
    for (int k0 = kbeg; k0 < kbeg + 512; k0 += 256) {
        for (int i = n; i < 8 * 256; i += 96) {
            int tt = i >> 8, kk = i & 255;
            xs[tt][kk] = g_xconv[(size_t)(t0 + tt) * D_INNER + k0 + kk];
        }
        __syncthreads();
#pragma unroll 8
        for (int kk = 0; kk < 256; ++kk) {
            float w = Wx[(size_t)(k0 + kk) * X_DBL_W + n];
#pragma unroll
            for (int tt = 0; tt < 8; ++tt) acc[tt] = fmaf(xs[tt][kk], w, acc[tt]);
        }
        __syncthreads();
    }
#pragma unroll
    for (int tt = 0; tt < 8; ++tt)
        g_xdp[((size_t)ks * L_SEQ + t0 + tt) * X_DBL_W + n] = acc[tt];
}

__global__ void xdbl_reduce() {
    int i = blockIdx.x * 256 + threadIdx.x;            // < 98304
    const int S = L_SEQ * X_DBL_W;
    g_xdbl[i] = g_xdp[i] + g_xdp[S + i] + g_xdp[2 * S + i] + g_xdp[3 * S + i];
}

// =====================================================================
// delta = softplus(dt @ W_dt + b_dt)
// =====================================================================
__global__ void delta_kernel(const float* __restrict__ Wdt,
                             const float* __restrict__ bdt) {
    __shared__ float dts[16][64];
    int d = blockIdx.x * 256 + threadIdx.x;
    int t0 = blockIdx.y * 16;

    for (int i = threadIdx.x; i < 16 * 64; i += 256) {
        int tt = i >> 6, kk = i & 63;
        dts[tt][kk] = g_xdbl[(t0 + tt) * X_DBL_W + kk];
    }
    __syncthreads();

    float bb = bdt[d];
    float acc[16];
#pragma unroll
    for (int tt = 0; tt < 16; ++tt) acc[tt] = bb;
#pragma unroll 4
    for (int k = 0; k < DT_RANK; ++k) {
        float w = Wdt[(size_t)k * D_INNER + d];
#pragma unroll
        for (int tt = 0; tt < 16; ++tt) acc[tt] = fmaf(dts[tt][k], w, acc[tt]);
    }
#pragma unroll
    for (int tt = 0; tt < 16; ++tt) {
        float a = acc[tt];
        float sp = (a > 20.f) ? a : log1pf(__expf(a));
        g_delta[(size_t)(t0 + tt) * D_INNER + d] = sp;
    }
}

// =====================================================================
// chunked selective scan (P1 summaries, P2 boundary states, P3 emit)
// =====================================================================
__global__ void scan_p1(const float* __restrict__ A_log) {
    int tid = threadIdx.x;
    int g = tid >> 4, n = tid & 15;
    int d = blockIdx.x * 8 + g;
    int c = blockIdx.y;

    float Aval = -__expf(A_log[d * N_STATE + n]);
    float P = 1.f, S = 0.f;
    int tbase = c * CHUNK;
#pragma unroll 8
    for (int i = 0; i < CHUNK; ++i) {
        int t = tbase + i;
        float dl = g_delta[(size_t)t * D_INNER + d];
        float u  = g_xconv[(size_t)t * D_INNER + d];
        float Bv = g_xdbl[t * X_DBL_W + DT_RANK + n];
        float dA = __expf(dl * Aval);
        S = fmaf(dA, S, dl * Bv * u);
        P *= dA;
    }
    int idx = (c * D_INNER + d) * N_STATE + n;
    g_P[idx] = P;
    g_S[idx] = S;
}

__global__ void scan_p2() {
    int dn = blockIdx.x * 256 + threadIdx.x;
    float h = 0.f;
#pragma unroll
    for (int c = 0; c < NCHUNK; ++c) {
        int idx = c * (D_INNER * N_STATE) + dn;
        g_h0[idx] = h;
        h = fmaf(g_P[idx], h, g_S[idx]);
    }
}

__global__ void scan_p3(const float* __restrict__ A_log,
                        const float* __restrict__ Dp) {
    int tid = threadIdx.x;
    int g = tid >> 4, n = tid & 15;
    int d = blockIdx.x * 8 + g;
    int c = blockIdx.y;

    float Aval = -__expf(A_log[d * N_STATE + n]);
    float Dd = Dp[d];
    float h = g_h0[(c * D_INNER + d) * N_STATE + n];
    int tbase = c * CHUNK;
#pragma unroll 4
    for (int i = 0; i < CHUNK; ++i) {
        int t = tbase + i;
        float dl = g_delta[(size_t)t * D_INNER + d];
        float u  = g_xconv[(size_t)t * D_INNER + d];
        float Bv = g_xdbl[t * X_DBL_W + DT_RANK + n];
        float Cv = g_xdbl[t * X_DBL_W + DT_RANK + N_STATE + n];

        float dA = __expf(dl * Aval);
        h = fmaf(dA, h, dl * Bv * u);
        float part = h * Cv;
        part += __shfl_xor_sync(0xffffffffu, part, 8, 16);
        part += __shfl_xor_sync(0xffffffffu, part, 4, 16);
        part += __shfl_xor_sync(0xffffffffu, part, 2, 16);
        part += __shfl_xor_sync(0xffffffffu, part, 1, 16);

        if (n == 0) {
            float r = g_xr[(size_t)t * 4096 + D_INNER + d];
            float sr = __fdividef(r, 1.f + __expf(-r));
            g_ysc[(size_t)t * D_INNER + d] = (part + u * Dd) * sr;
        }
    }
}

// =====================================================================
// launch
// =====================================================================
template <typename T>
static T* sym_addr(const void* sym) {
    void* p = nullptr;
    cudaGetSymbolAddress(&p, sym);
    return (T*)p;
}

extern "C" void kernel_launch(void* const* d_in, const int* in_sizes, int n_in,
                              void* d_out, int out_size) {
    const float* x      = (const float*)d_in[0];
    const float* W_in   = (const float*)d_in[1];
    const float* conv_w = (const float*)d_in[2];
    const float* conv_b = (const float*)d_in[3];
    const float* W_x    = (const float*)d_in[4];
    const float* W_dt   = (const float*)d_in[5];
    const float* b_dt   = (const float*)d_in[6];
    const float* A_log  = (const float*)d_in[7];
    const float* Dvec   = (const float*)d_in[8];
    const float* W_out  = (const float*)d_in[9];
    float* out = (float*)d_out;

    float* xr   = sym_addr<float>(g_xr);
    float* ysc  = sym_addr<float>(g_ysc);
    float* tmp  = sym_addr<float>(g_tmp);
    __half* ae  = sym_addr<__half>(g_aext);
    __half* b1e = sym_addr<__half>(g_b1e);
    __half* b2e = sym_addr<__half>(g_b2e);

    // --- conversions (A-split: [Ah|Al]; B-split: [Bh;Bl;Bh] K-major) ---
    cvt_split<<<(1024 * 1024 / 2 + 255) / 256, 256>>>(x, ae, 1024, 1024);
    cvt_Bsplit<<<1024 * 4096 / 512, 256>>>(W_in, b1e, 1024 * 4096);
    cvt_Bsplit<<<2048 * 1024 / 512, 256>>>(W_out, b2e, 2048 * 1024);

    // 1) x_and_res = x @ W_in   [1024,4096]; Kext=3072, korig=1024
    gemm_mma<<<dim3(4096 / GBN, 1024 / GBM, 1), 256>>>(
        ae, b1e, xr, nullptr, nullptr, nullptr, 4096, 3072, 1024, 2048, 4096);

    // 2) conv + silu
    conv_silu_kernel<<<(L_SEQ * D_INNER + 255) / 256, 256>>>(conv_w, conv_b);

    // 3) x_dbl (K-split x4 + reduce)
    xdbl_kernel<<<dim3(L_SEQ / 8, 4), X_DBL_W>>>(W_x);
    xdbl_reduce<<<L_SEQ * X_DBL_W / 256, 256>>>();

    // 4) delta
    delta_kernel<<<dim3(D_INNER / 256, L_SEQ / 16), 256>>>(W_dt, b_dt);

    // 5) chunked selective scan
    scan_p1<<<dim3(D_INNER / 8, NCHUNK), 128>>>(A_log);
    scan_p2<<<D_INNER * N_STATE / 256, 256>>>();
    scan_p3<<<dim3(D_INNER / 8, NCHUNK), 128>>>(A_log, Dvec);

    // 6) out = ysc @ W_out  [1024,1024]; Kext=6144, korig=2048, split-K z=4
    cvt_split<<<(1024 * 2048 / 2 + 255) / 256, 256>>>(ysc, ae, 1024, 2048);
    gemm_mma<<<dim3(1024 / GBN, 1024 / GBM, 4), 256>>>(
        ae, b2e, out, tmp, tmp + 1024 * 1024, tmp + 2 * 1024 * 1024,
        1024, 6144, 2048, 4096, 1024);
    add4_kernel<<<1024 * 1024 / 1024, 256>>>(out);
}

// round 14
// speedup vs baseline: 3.7163x; 1.0657x over previous
#include <cuda_runtime.h>
#include <cuda_fp16.h>
#include <cstdint>

// ---------------- problem constants ----------------
#define L_SEQ    1024
#define D_MODEL  1024
#define D_INNER  2048
#define N_STATE  16
#define DT_RANK  64
#define X_DBL_W  96   // DT_RANK + 2*N_STATE
#define CHUNK    32
#define NCHUNK   (L_SEQ / CHUNK)   // 32

// ---------------- fp32 scratch ----------------
__device__ float g_xr[L_SEQ * 2 * D_INNER];      // x_and_res [1024,4096]
__device__ float g_xconv[L_SEQ * D_INNER];       // [1024,2048]
__device__ float g_xdbl[L_SEQ * X_DBL_W];        // [1024,96]
__device__ float g_xdp[4 * L_SEQ * X_DBL_W];     // xdbl K-split partials
__device__ float g_delta[L_SEQ * D_INNER];       // [1024,2048]
__device__ float g_ysc[L_SEQ * D_INNER];         // (y+u*D)*silu(res)
__device__ float g_tmp[3 * 1024 * 1024];         // GEMM2 split-K partials

// ---------------- chunked-scan scratch ----------------
__device__ float g_P[NCHUNK * D_INNER * N_STATE];
__device__ float g_S[NCHUNK * D_INNER * N_STATE];
__device__ float g_h0[NCHUNK * D_INNER * N_STATE];

// ---------------- fp16 split scratch ----------------
// A = [Ah | Al] (M x 2K) row-major; B = [Bh ; Bl] (2K x N) K-major
__device__ __half g_aext[1024 * 4096];           // max: ysc split (1024 x 2*2048)
__device__ __half g_b1e[2048 * 4096];            // W_in split  [2*1024, 4096]
__device__ __half g_b2e[4096 * 1024];            // W_out split [2*2048, 1024]

// =====================================================================
// base-PTX helpers (compute_103-safe)
// =====================================================================
__device__ __forceinline__ uint32_t smem_u32(const void* p) {
    uint32_t a;
    asm("{ .reg .u64 t; cvta.to.shared.u64 t, %1; cvt.u32.u64 %0, t; }" : "=r"(a) : "l"(p));
    return a;
}
__device__ __forceinline__ void cp16(uint32_t s, const void* g) {
    asm volatile("cp.async.cg.shared.global [%0], [%1], 16;" :: "r"(s), "l"(g));
}
#define CP_COMMIT() asm volatile("cp.async.commit_group;" ::: "memory")

#define LDSM_X4(r0, r1, r2, r3, addr) \
    asm volatile("ldmatrix.sync.aligned.m8n8.x4.shared.b16 {%0,%1,%2,%3}, [%4];" \
        : "=r"(r0), "=r"(r1), "=r"(r2), "=r"(r3) : "r"(addr))
#define LDSM_X2_T(r0, r1, addr) \
    asm volatile("ldmatrix.sync.aligned.m8n8.x2.trans.shared.b16 {%0,%1}, [%2];" \
        : "=r"(r0), "=r"(r1) : "r"(addr))
#define MMA16816(d, a, b) \
    asm volatile("mma.sync.aligned.m16n8k16.row.col.f32.f16.f16.f32 " \
        "{%0,%1,%2,%3}, {%4,%5,%6,%7}, {%8,%9}, {%0,%1,%2,%3};" \
        : "+f"((d)[0]), "+f"((d)[1]), "+f"((d)[2]), "+f"((d)[3]) \
        : "r"((a)[0]), "r"((a)[1]), "r"((a)[2]), "r"((a)[3]), "r"((b)[0]), "r"((b)[1]))

// =====================================================================
// HMMA GEMM over extended K (3 split-terms folded into K):
//   ke<K      : Ah*Bh   kA=ke      kB=ke
//   K<=ke<2K  : Ah*Bl   kA=ke-K    kB=ke      (rows K..2K of B = Bl)
//   2K<=ke<3K : Al*Bh   kA=ke-K    kB=ke-2K
// A row-major [M,2K] (lda), B K-major [2K,N] (ldb).
// tile 128x128x64, 8 warps, dynamic smem double buffer.
// split-K over gridDim.z -> C0..C3.
// =====================================================================
#define GBM 128
#define GBN 128
#define A_STR 144                  // bytes: 64 halves + 8 pad
#define B_STR 272                  // bytes: 128 halves + 8 pad
#define A_BYTES (128 * A_STR)      // 18432
#define B_BYTES (64 * B_STR)       // 17408
#define STAGE_B (A_BYTES + B_BYTES)   // 35840
#define GSMEM (2 * STAGE_B)           // 71680

__global__ void __launch_bounds__(256, 2) gemm_mma(
    const __half* __restrict__ A, const __half* __restrict__ B,
    float* __restrict__ C0, float* __restrict__ C1,
    float* __restrict__ C2, float* __restrict__ C3,
    int N, int Kext, int korig, int lda, int ldb) {
    extern __shared__ __align__(16) char smem[];
    const uint32_t sbase = smem_u32(smem);
    const int tid = threadIdx.x;
    const int lane = tid & 31, wid = tid >> 5;
    const int m0 = blockIdx.y * GBM, n0 = blockIdx.x * GBN;
    const int z = blockIdx.z;
    const int Kz = Kext / gridDim.z;
    const int ke0 = z * Kz;
    float* C = (z == 0) ? C0 : (z == 1) ? C1 : (z == 2) ? C2 : C3;

    const __half* Ag = A + (size_t)m0 * lda;
    const __half* Bg = B + n0;

    const int wm = (wid & 1) * 64;
    const int wn = (wid >> 1) * 32;

    float acc[4][4][4];
#pragma unroll
    for (int i = 0; i < 4; ++i)
#pragma unroll
        for (int j = 0; j < 4; ++j)
#pragma unroll
            for (int q = 0; q < 4; ++q) acc[i][j][q] = 0.f;

    const int nIter = Kz >> 6;

    auto load_tile = [&](int it, int stage) {
        int kt = ke0 + (it << 6);
        int kA = (kt < korig) ? kt : kt - korig;
        int kB = (kt < 2 * korig) ? kt : kt - 2 * korig;
        uint32_t sA = sbase + stage * STAGE_B;
        uint32_t sB = sA + A_BYTES;
#pragma unroll
        for (int c = tid; c < 2048; c += 256) {
            if (c < 1024) {
                int r = c >> 3, col = (c & 7) * 16;
                cp16(sA + r * A_STR + col,
                     (const char*)(Ag + (size_t)r * lda + kA) + col);
            } else {
                int cc = c - 1024;
                int r = cc >> 4, col = (cc & 15) * 16;
                cp16(sB + r * B_STR + col,
                     (const char*)(Bg + (size_t)(kB + r) * ldb) + col);
            }
        }
    };

    load_tile(0, 0);
    CP_COMMIT();

    const uint32_t aOff = (wm + (lane & 15)) * A_STR + (lane >> 4) * 16;
    const uint32_t bOff = (lane & 15) * B_STR + wn * 2;

    for (int it = 0; it < nIter; ++it) {
        if (it + 1 < nIter) {
            load_tile(it + 1, (it + 1) & 1);
            CP_COMMIT();
            asm volatile("cp.async.wait_group 1;" ::: "memory");
        } else {
            asm volatile("cp.async.wait_group 0;" ::: "memory");
        }
        __syncthreads();

        uint32_t sA = sbase + (it & 1) * STAGE_B + aOff;
        uint32_t sB = sbase + (it & 1) * STAGE_B + A_BYTES + bOff;
#pragma unroll
        for (int ks = 0; ks < 4; ++ks) {
            uint32_t a[4][4], b[4][2];
#pragma unroll
            for (int mt = 0; mt < 4; ++mt)
                LDSM_X4(a[mt][0], a[mt][1], a[mt][2], a[mt][3],
                        sA + mt * (16 * A_STR) + ks * 32);
#pragma unroll
            for (int nt = 0; nt < 4; ++nt)
                LDSM_X2_T(b[nt][0], b[nt][1], sB + ks * (16 * B_STR) + nt * 16);
#pragma unroll
            for (int mt = 0; mt < 4; ++mt)
#pragma unroll
                for (int nt = 0; nt < 4; ++nt)
                    MMA16816(acc[mt][nt], a[mt], b[nt]);
        }
        __syncthreads();
    }

    const int qr = lane >> 2, qc = (lane & 3) * 2;
#pragma unroll
    for (int mt = 0; mt < 4; ++mt) {
        int row = m0 + wm + mt * 16 + qr;
#pragma unroll
        for (int nt = 0; nt < 4; ++nt) {
            int col = n0 + wn + nt * 8 + qc;
            *(float2*)(C + (size_t)row * N + col) =
                make_float2(acc[mt][nt][0], acc[mt][nt][1]);
            *(float2*)(C + (size_t)(row + 8) * N + col) =
                make_float2(acc[mt][nt][2], acc[mt][nt][3]);
        }
    }
}

// out += t0 + t1 + t2   (GEMM2 split-K reduction, 1024x1024)
__global__ void add4_kernel(float* __restrict__ out) {
    int i = (blockIdx.x * 256 + threadIdx.x) * 4;
    float4 a = *(const float4*)(out + i);
    float4 b = *(const float4*)(g_tmp + i);
    float4 c = *(const float4*)(g_tmp + 1024 * 1024 + i);
    float4 d = *(const float4*)(g_tmp + 2 * 1024 * 1024 + i);
    a.x += b.x + c.x + d.x; a.y += b.y + c.y + d.y;
    a.z += b.z + c.z + d.z; a.w += b.w + c.w + d.w;
    *(float4*)(out + i) = a;
}

// =====================================================================
// fp32 [R,C] -> fp16 A-split [R,2C] = [Ah | Al]
// =====================================================================
__global__ void cvt_split(const float* __restrict__ A, __half* __restrict__ out,
                          int R, int C) {
    int i2 = (blockIdx.x * 256 + threadIdx.x) * 2;
    if (i2 >= R * C) return;
    int r = i2 / C, c = i2 - r * C;
    float2 v = *(const float2*)(A + i2);
    __half h0 = __float2half(v.x), h1 = __float2half(v.y);
    __half2 hh; hh.x = h0; hh.y = h1;
    __half2 ll;
    ll.x = __float2half(v.x - __half2float(h0));
    ll.y = __float2half(v.y - __half2float(h1));
    __half* row = out + (size_t)r * 2 * C;
    *(__half2*)(row + c) = hh;
    *(__half2*)(row + C + c) = ll;
}

// fp32 W[K,N] -> fp16 B-split [2K,N] = [Bh ; Bl], coalesced half2
__global__ void cvt_Bsplit(const float* __restrict__ W, __half* __restrict__ out,
                           int KN) {
    int i2 = (blockIdx.x * 256 + threadIdx.x) * 2;
    if (i2 >= KN) return;
    float2 v = *(const float2*)(W + i2);
    __half h0 = __float2half(v.x), h1 = __float2half(v.y);
    __half2 hh; hh.x = h0; hh.y = h1;
    __half2 ll;
    ll.x = __float2half(v.x - __half2float(h0));
    ll.y = __float2half(v.y - __half2float(h1));
    *(__half2*)(out + i2) = hh;
    *(__half2*)(out + KN + i2) = ll;
}

// =====================================================================
// fused: causal depthwise conv (K=4) + SiLU  +  x_dbl partial GEMM
// block (t0 = bx*8 rows, ks = by in 0..3 -> d range of 512)
// computes xconv tile in smem (and writes g_xconv), then dots with W_x
// =====================================================================
__global__ void xdbl_conv(const float* __restrict__ Wx,
                          const float* __restrict__ conv_w,
                          const float* __restrict__ conv_b) {
    __shared__ float xs[8][256];
    int t0 = blockIdx.x * 8;
    int ks = blockIdx.y;                               // 0..3
    int n = threadIdx.x;                               // 0..95
    float acc[8];
#pragma unroll
    for (int tt = 0; tt < 8; ++tt) acc[tt] = 0.f;

    int kbeg = ks * 512;
    for (int k0 = kbeg; k0 < kbeg + 512; k0 += 256) {
        for (int i = n; i < 8 * 256; i += 96) {
            int tt = i >> 8, kk = i & 255;
            int t = t0 + tt, d = k0 + kk;
            float4 w = *(const float4*)(conv_w + d * 4);
            float s = conv_b[d];
            if (t >= 3) s += g_xr[(size_t)(t - 3) * 4096 + d] * w.x;
            if (t >= 2) s += g_xr[(size_t)(t - 2) * 4096 + d] * w.y;
            if (t >= 1) s += g_xr[(size_t)(t - 1) * 4096 + d] * w.z;
            s += g_xr[(size_t)t * 4096 + d] * w.w;
            float v = __fdividef(s, 1.f + __expf(-s));
            xs[tt][kk] = v;
            g_xconv[(size_t)t * D_INNER + d] = v;
        }
        __syncthreads();
#pragma unroll 8
        for (int kk = 0; kk < 256; ++kk) {
            float w = Wx[(size_t)(k0 + kk) * X_DBL_W + n];
#pragma unroll
            for (int tt = 0; tt < 8; ++tt) acc[tt] = fmaf(xs[tt][kk], w, acc[tt]);
        }
        __syncthreads();
    }
#pragma unroll
    for (int tt = 0; tt < 8; ++tt)
        g_xdp[((size_t)ks * L_SEQ + t0 + tt) * X_DBL_W + n] = acc[tt];
}

__global__ void xdbl_reduce() {
    int i = blockIdx.x * 256 + threadIdx.x;            // < 98304
    const int S = L_SEQ * X_DBL_W;
    g_xdbl[i] = g_xdp[i] + g_xdp[S + i] + g_xdp[2 * S + i] + g_xdp[3 * S + i];
}

// =====================================================================
// delta = softplus(dt @ W_dt + b_dt)
// =====================================================================
__global__ void delta_kernel(const float* __restrict__ Wdt,
                             const float* __restrict__ bdt) {
    __shared__ float dts[16][64];
    int d = blockIdx.x * 256 + threadIdx.x;
    int t0 = blockIdx.y * 16;

    for (int i = threadIdx.x; i < 16 * 64; i += 256) {
        int tt = i >> 6, kk = i & 63;
        dts[tt][kk] = g_xdbl[(t0 + tt) * X_DBL_W + kk];
    }
    __syncthreads();

    float bb = bdt[d];
    float acc[16];
#pragma unroll
    for (int tt = 0; tt < 16; ++tt) acc[tt] = bb;
#pragma unroll 4
    for (int k = 0; k < DT_RANK; ++k) {
        float w = Wdt[(size_t)k * D_INNER + d];
#pragma unroll
        for (int tt = 0; tt < 16; ++tt) acc[tt] = fmaf(dts[tt][k], w, acc[tt]);
    }
#pragma unroll
    for (int tt = 0; tt < 16; ++tt) {
        float a = acc[tt];
        float sp = (a > 20.f) ? a : log1pf(__expf(a));
        g_delta[(size_t)(t0 + tt) * D_INNER + d] = sp;
    }
}

// =====================================================================
// chunked selective scan (P1 summaries, P2 boundary states, P3 emit)
// =====================================================================
__global__ void scan_p1(const float* __restrict__ A_log) {
    int tid = threadIdx.x;
    int g = tid >> 4, n = tid & 15;
    int d = blockIdx.x * 8 + g;
    int c = blockIdx.y;

    float Aval = -__expf(A_log[d * N_STATE + n]);
    float P = 1.f, S = 0.f;
    int tbase = c * CHUNK;
#pragma unroll 8
    for (int i = 0; i < CHUNK; ++i) {
        int t = tbase + i;
        float dl = g_delta[(size_t)t * D_INNER + d];
        float u  = g_xconv[(size_t)t * D_INNER + d];
        float Bv = g_xdbl[t * X_DBL_W + DT_RANK + n];
        float dA = __expf(dl * Aval);
        S = fmaf(dA, S, dl * Bv * u);
        P *= dA;
    }
    int idx = (c * D_INNER + d) * N_STATE + n;
    g_P[idx] = P;
    g_S[idx] = S;
}

__global__ void scan_p2() {
    int dn = blockIdx.x * 256 + threadIdx.x;
    float h = 0.f;
#pragma unroll
    for (int c = 0; c < NCHUNK; ++c) {
        int idx = c * (D_INNER * N_STATE) + dn;
        g_h0[idx] = h;
        h = fmaf(g_P[idx], h, g_S[idx]);
    }
}

__global__ void scan_p3(const float* __restrict__ A_log,
                        const float* __restrict__ Dp) {
    int tid = threadIdx.x;
    int g = tid >> 4, n = tid & 15;
    int d = blockIdx.x * 8 + g;
    int c = blockIdx.y;

    float Aval = -__expf(A_log[d * N_STATE + n]);
    float Dd = Dp[d];
    float h = g_h0[(c * D_INNER + d) * N_STATE + n];
    int tbase = c * CHUNK;
#pragma unroll 4
    for (int i = 0; i < CHUNK; ++i) {
        int t = tbase + i;
        float dl = g_delta[(size_t)t * D_INNER + d];
        float u  = g_xconv[(size_t)t * D_INNER + d];
        float Bv = g_xdbl[t * X_DBL_W + DT_RANK + n];
        float Cv = g_xdbl[t * X_DBL_W + DT_RANK + N_STATE + n];

        float dA = __expf(dl * Aval);
        h = fmaf(dA, h, dl * Bv * u);
        float part = h * Cv;
        part += __shfl_xor_sync(0xffffffffu, part, 8, 16);
        part += __shfl_xor_sync(0xffffffffu, part, 4, 16);
        part += __shfl_xor_sync(0xffffffffu, part, 2, 16);
        part += __shfl_xor_sync(0xffffffffu, part, 1, 16);

        if (n == 0) {
            float r = g_xr[(size_t)t * 4096 + D_INNER + d];
            float sr = __fdividef(r, 1.f + __expf(-r));
            g_ysc[(size_t)t * D_INNER + d] = (part + u * Dd) * sr;
        }
    }
}

// =====================================================================
// launch
// =====================================================================
template <typename T>
static T* sym_addr(const void* sym) {
    void* p = nullptr;
    cudaGetSymbolAddress(&p, sym);
    return (T*)p;
}

extern "C" void kernel_launch(void* const* d_in, const int* in_sizes, int n_in,
                              void* d_out, int out_size) {
    const float* x      = (const float*)d_in[0];
    const float* W_in   = (const float*)d_in[1];
    const float* conv_w = (const float*)d_in[2];
    const float* conv_b = (const float*)d_in[3];
    const float* W_x    = (const float*)d_in[4];
    const float* W_dt   = (const float*)d_in[5];
    const float* b_dt   = (const float*)d_in[6];
    const float* A_log  = (const float*)d_in[7];
    const float* Dvec   = (const float*)d_in[8];
    const float* W_out  = (const float*)d_in[9];
    float* out = (float*)d_out;

    cudaFuncSetAttribute(gemm_mma, cudaFuncAttributeMaxDynamicSharedMemorySize, GSMEM);

    float* xr   = sym_addr<float>(g_xr);
    float* ysc  = sym_addr<float>(g_ysc);
    float* tmp  = sym_addr<float>(g_tmp);
    __half* ae  = sym_addr<__half>(g_aext);
    __half* b1e = sym_addr<__half>(g_b1e);
    __half* b2e = sym_addr<__half>(g_b2e);

    // --- conversions (A-split: [Ah|Al]; B-split: [Bh;Bl] K-major) ---
    cvt_split<<<(1024 * 1024 / 2 + 255) / 256, 256>>>(x, ae, 1024, 1024);
    cvt_Bsplit<<<1024 * 4096 / 512, 256>>>(W_in, b1e, 1024 * 4096);
    cvt_Bsplit<<<2048 * 1024 / 512, 256>>>(W_out, b2e, 2048 * 1024);

    // 1) x_and_res = x @ W_in   [1024,4096]; Kext=3072, korig=1024
    gemm_mma<<<dim3(4096 / GBN, 1024 / GBM, 1), 256, GSMEM>>>(
        ae, b1e, xr, nullptr, nullptr, nullptr, 4096, 3072, 1024, 2048, 4096);

    // 2+3) fused conv+silu+x_dbl (K-split x4) + reduce
    xdbl_conv<<<dim3(L_SEQ / 8, 4), X_DBL_W>>>(W_x, conv_w, conv_b);
    xdbl_reduce<<<L_SEQ * X_DBL_W / 256, 256>>>();

    // 4) delta
    delta_kernel<<<dim3(D_INNER / 256, L_SEQ / 16), 256>>>(W_dt, b_dt);

    // 5) chunked selective scan
    scan_p1<<<dim3(D_INNER / 8, NCHUNK), 128>>>(A_log);
    scan_p2<<<D_INNER * N_STATE / 256, 256>>>();
    scan_p3<<<dim3(D_INNER / 8, NCHUNK), 128>>>(A_log, Dvec);

    // 6) out = ysc @ W_out  [1024,1024]; Kext=6144, korig=2048, split-K z=4
    cvt_split<<<(1024 * 2048 / 2 + 255) / 256, 256>>>(ysc, ae, 1024, 2048);
    gemm_mma<<<dim3(1024 / GBN, 1024 / GBM, 4), 256, GSMEM>>>(
        ae, b2e, out, tmp, tmp + 1024 * 1024, tmp + 2 * 1024 * 1024,
        1024, 6144, 2048, 4096, 1024);
    add4_kernel<<<1024 * 1024 / 1024, 256>>>(out);
}

// round 15
// speedup vs baseline: 3.7565x; 1.0108x over previous
#include <cuda_runtime.h>
#include <cuda_fp16.h>
#include <cstdint>

// ---------------- problem constants ----------------
#define L_SEQ    1024
#define D_MODEL  1024
#define D_INNER  2048
#define N_STATE  16
#define DT_RANK  64
#define X_DBL_W  96   // DT_RANK + 2*N_STATE
#define CHUNK    32
#define NCHUNK   (L_SEQ / CHUNK)   // 32

// ---------------- fp32 scratch ----------------
__device__ float g_xr[L_SEQ * 2 * D_INNER];      // x_and_res [1024,4096]
__device__ float g_xconv[L_SEQ * D_INNER];       // [1024,2048]
__device__ float g_xdbl[L_SEQ * X_DBL_W];        // [1024,96]
__device__ float g_xdp[4 * L_SEQ * X_DBL_W];     // xdbl K-split partials
__device__ float g_delta[L_SEQ * D_INNER];       // [1024,2048]
__device__ float g_tmp[3 * 1024 * 1024];         // GEMM2 split-K partials

// ---------------- chunked-scan scratch ----------------
__device__ float g_P[NCHUNK * D_INNER * N_STATE];
__device__ float g_S[NCHUNK * D_INNER * N_STATE];
__device__ float g_h0[NCHUNK * D_INNER * N_STATE];

// ---------------- fp16 split scratch ----------------
// A = [Ah | Al] (M x 2K) row-major; B = [Bh ; Bl] (2K x N) K-major
__device__ __half g_aext[1024 * 4096];           // x split, then ysc split
__device__ __half g_b1e[2048 * 4096];            // W_in split  [2*1024, 4096]
__device__ __half g_b2e[4096 * 1024];            // W_out split [2*2048, 1024]

// =====================================================================
// base-PTX helpers (compute_103-safe)
// =====================================================================
__device__ __forceinline__ uint32_t smem_u32(const void* p) {
    uint32_t a;
    asm("{ .reg .u64 t; cvta.to.shared.u64 t, %1; cvt.u32.u64 %0, t; }" : "=r"(a) : "l"(p));
    return a;
}
__device__ __forceinline__ void cp16(uint32_t s, const void* g) {
    asm volatile("cp.async.cg.shared.global [%0], [%1], 16;" :: "r"(s), "l"(g));
}
#define CP_COMMIT() asm volatile("cp.async.commit_group;" ::: "memory")

#define LDSM_X4(r0, r1, r2, r3, addr) \
    asm volatile("ldmatrix.sync.aligned.m8n8.x4.shared.b16 {%0,%1,%2,%3}, [%4];" \
        : "=r"(r0), "=r"(r1), "=r"(r2), "=r"(r3) : "r"(addr))
#define LDSM_X2_T(r0, r1, addr) \
    asm volatile("ldmatrix.sync.aligned.m8n8.x2.trans.shared.b16 {%0,%1}, [%2];" \
        : "=r"(r0), "=r"(r1) : "r"(addr))
#define MMA16816(d, a, b) \
    asm volatile("mma.sync.aligned.m16n8k16.row.col.f32.f16.f16.f32 " \
        "{%0,%1,%2,%3}, {%4,%5,%6,%7}, {%8,%9}, {%0,%1,%2,%3};" \
        : "+f"((d)[0]), "+f"((d)[1]), "+f"((d)[2]), "+f"((d)[3]) \
        : "r"((a)[0]), "r"((a)[1]), "r"((a)[2]), "r"((a)[3]), "r"((b)[0]), "r"((b)[1]))

// =====================================================================
// HMMA GEMM over extended K (3 split-terms folded into K):
//   ke<K      : Ah*Bh   kA=ke      kB=ke
//   K<=ke<2K  : Ah*Bl   kA=ke-K    kB=ke
//   2K<=ke<3K : Al*Bh   kA=ke-K    kB=ke-2K
// A row-major [M,2K] (lda), B K-major [2K,N] (ldb).
// tile 128x128x64, 8 warps, 3-stage cp.async pipeline (1 sync/iter).
// split-K over gridDim.z -> C0..C3.
// =====================================================================
#define GBM 128
#define GBN 128
#define A_STR 144                  // bytes: 64 halves + 8 pad
#define B_STR 272                  // bytes: 128 halves + 8 pad
#define A_BYTES (128 * A_STR)      // 18432
#define B_BYTES (64 * B_STR)       // 17408
#define STAGE_B (A_BYTES + B_BYTES)   // 35840
#define NSTAGE 3
#define GSMEM (NSTAGE * STAGE_B)      // 107520

__global__ void __launch_bounds__(256, 2) gemm_mma(
    const __half* __restrict__ A, const __half* __restrict__ B,
    float* __restrict__ C0, float* __restrict__ C1,
    float* __restrict__ C2, float* __restrict__ C3,
    int N, int Kext, int korig, int lda, int ldb) {
    extern __shared__ __align__(16) char smem[];
    const uint32_t sbase = smem_u32(smem);
    const int tid = threadIdx.x;
    const int lane = tid & 31, wid = tid >> 5;
    const int m0 = blockIdx.y * GBM, n0 = blockIdx.x * GBN;
    const int z = blockIdx.z;
    const int Kz = Kext / gridDim.z;
    const int ke0 = z * Kz;
    float* C = (z == 0) ? C0 : (z == 1) ? C1 : (z == 2) ? C2 : C3;

    const __half* Ag = A + (size_t)m0 * lda;
    const __half* Bg = B + n0;

    const int wm = (wid & 1) * 64;
    const int wn = (wid >> 1) * 32;

    float acc[4][4][4];
#pragma unroll
    for (int i = 0; i < 4; ++i)
#pragma unroll
        for (int j = 0; j < 4; ++j)
#pragma unroll
            for (int q = 0; q < 4; ++q) acc[i][j][q] = 0.f;

    const int nIter = Kz >> 6;

    auto load_tile = [&](int it, int stage) {
        int kt = ke0 + (it << 6);
        int kA = (kt < korig) ? kt : kt - korig;
        int kB = (kt < 2 * korig) ? kt : kt - 2 * korig;
        uint32_t sA = sbase + stage * STAGE_B;
        uint32_t sB = sA + A_BYTES;
#pragma unroll
        for (int c = tid; c < 2048; c += 256) {
            if (c < 1024) {
                int r = c >> 3, col = (c & 7) * 16;
                cp16(sA + r * A_STR + col,
                     (const char*)(Ag + (size_t)r * lda + kA) + col);
            } else {
                int cc = c - 1024;
                int r = cc >> 4, col = (cc & 15) * 16;
                cp16(sB + r * B_STR + col,
                     (const char*)(Bg + (size_t)(kB + r) * ldb) + col);
            }
        }
    };

    // prologue: stages 0 and 1 in flight
    load_tile(0, 0);
    CP_COMMIT();
    load_tile(1, 1);
    CP_COMMIT();

    const uint32_t aOff = (wm + (lane & 15)) * A_STR + (lane >> 4) * 16;
    const uint32_t bOff = (lane & 15) * B_STR + wn * 2;

    int cs = 0;           // compute stage = it % 3
    int ls = 2;           // load stage    = (it+2) % 3
    for (int it = 0; it < nIter; ++it) {
        // complete tile `it` (keep tile it+1 pending)
        asm volatile("cp.async.wait_group 1;" ::: "memory");
        __syncthreads();   // publish loads; also fences compute(it-1) before ls overwrite

        if (it + 2 < nIter) load_tile(it + 2, ls);
        CP_COMMIT();       // empty commit at tail keeps group accounting uniform

        uint32_t sA = sbase + cs * STAGE_B + aOff;
        uint32_t sB = sbase + cs * STAGE_B + A_BYTES + bOff;
#pragma unroll
        for (int ks = 0; ks < 4; ++ks) {
            uint32_t a[4][4], b[4][2];
#pragma unroll
            for (int mt = 0; mt < 4; ++mt)
                LDSM_X4(a[mt][0], a[mt][1], a[mt][2], a[mt][3],
                        sA + mt * (16 * A_STR) + ks * 32);
#pragma unroll
            for (int nt = 0; nt < 4; ++nt)
                LDSM_X2_T(b[nt][0], b[nt][1], sB + ks * (16 * B_STR) + nt * 16);
#pragma unroll
            for (int mt = 0; mt < 4; ++mt)
#pragma unroll
                for (int nt = 0; nt < 4; ++nt)
                    MMA16816(acc[mt][nt], a[mt], b[nt]);
        }
        cs = (cs == 2) ? 0 : cs + 1;
        ls = (ls == 2) ? 0 : ls + 1;
    }

    const int qr = lane >> 2, qc = (lane & 3) * 2;
#pragma unroll
    for (int mt = 0; mt < 4; ++mt) {
        int row = m0 + wm + mt * 16 + qr;
#pragma unroll
        for (int nt = 0; nt < 4; ++nt) {
            int col = n0 + wn + nt * 8 + qc;
            *(float2*)(C + (size_t)row * N + col) =
                make_float2(acc[mt][nt][0], acc[mt][nt][1]);
            *(float2*)(C + (size_t)(row + 8) * N + col) =
                make_float2(acc[mt][nt][2], acc[mt][nt][3]);
        }
    }
}

// out += t0 + t1 + t2   (GEMM2 split-K reduction, 1024x1024)
__global__ void add4_kernel(float* __restrict__ out) {
    int i = (blockIdx.x * 256 + threadIdx.x) * 4;
    float4 a = *(const float4*)(out + i);
    float4 b = *(const float4*)(g_tmp + i);
    float4 c = *(const float4*)(g_tmp + 1024 * 1024 + i);
    float4 d = *(const float4*)(g_tmp + 2 * 1024 * 1024 + i);
    a.x += b.x + c.x + d.x; a.y += b.y + c.y + d.y;
    a.z += b.z + c.z + d.z; a.w += b.w + c.w + d.w;
    *(float4*)(out + i) = a;
}

// =====================================================================
// merged conversion kernel (one launch):
//   blocks [0,2048)      : x  [1024,1024]  -> g_aext A-split [Ah|Al]
//   blocks [2048,10240)  : W_in  (4M elem) -> g_b1e  B-split [Bh;Bl]
//   blocks [10240,14336) : W_out (2M elem) -> g_b2e  B-split [Bh;Bl]
// =====================================================================
__device__ __forceinline__ void split2(float2 v, __half2& hh, __half2& ll) {
    __half h0 = __float2half(v.x), h1 = __float2half(v.y);
    hh.x = h0; hh.y = h1;
    ll.x = __float2half(v.x - __half2float(h0));
    ll.y = __float2half(v.y - __half2float(h1));
}

__global__ void cvt_all(const float* __restrict__ x,
                        const float* __restrict__ W_in,
                        const float* __restrict__ W_out) {
    int b = blockIdx.x;
    if (b < 2048) {
        int i2 = (b * 256 + threadIdx.x) * 2;          // < 1M
        const int C = 1024;
        int r = i2 >> 10, c = i2 & 1023;
        __half2 hh, ll;
        split2(*(const float2*)(x + i2), hh, ll);
        __half* row = g_aext + (size_t)r * 2 * C;
        *(__half2*)(row + c) = hh;
        *(__half2*)(row + C + c) = ll;
    } else if (b < 10240) {
        int i2 = ((b - 2048) * 256 + threadIdx.x) * 2; // < 4M
        const int KN = 1024 * 4096;
        __half2 hh, ll;
        split2(*(const float2*)(W_in + i2), hh, ll);
        *(__half2*)(g_b1e + i2) = hh;
        *(__half2*)(g_b1e + KN + i2) = ll;
    } else {
        int i2 = ((b - 10240) * 256 + threadIdx.x) * 2; // < 2M
        const int KN = 2048 * 1024;
        __half2 hh, ll;
        split2(*(const float2*)(W_out + i2), hh, ll);
        *(__half2*)(g_b2e + i2) = hh;
        *(__half2*)(g_b2e + KN + i2) = ll;
    }
}

// =====================================================================
// fused: causal depthwise conv (K=4) + SiLU  +  x_dbl partial GEMM
// =====================================================================
__global__ void xdbl_conv(const float* __restrict__ Wx,
                          const float* __restrict__ conv_w,
                          const float* __restrict__ conv_b) {
    __shared__ float xs[8][256];
    int t0 = blockIdx.x * 8;
    int ks = blockIdx.y;                               // 0..3
    int n = threadIdx.x;                               // 0..95
    float acc[8];
#pragma unroll
    for (int tt = 0; tt < 8; ++tt) acc[tt] = 0.f;

    int kbeg = ks * 512;
    for (int k0 = kbeg; k0 < kbeg + 512; k0 += 256) {
        for (int i = n; i < 8 * 256; i += 96) {
            int tt = i >> 8, kk = i & 255;
            int t = t0 + tt, d = k0 + kk;
            float4 w = *(const float4*)(conv_w + d * 4);
            float s = conv_b[d];
            if (t >= 3) s += g_xr[(size_t)(t - 3) * 4096 + d] * w.x;
            if (t >= 2) s += g_xr[(size_t)(t - 2) * 4096 + d] * w.y;
            if (t >= 1) s += g_xr[(size_t)(t - 1) * 4096 + d] * w.z;
            s += g_xr[(size_t)t * 4096 + d] * w.w;
            float v = __fdividef(s, 1.f + __expf(-s));
            xs[tt][kk] = v;
            g_xconv[(size_t)t * D_INNER + d] = v;
        }
        __syncthreads();
#pragma unroll 8
        for (int kk = 0; kk < 256; ++kk) {
            float w = Wx[(size_t)(k0 + kk) * X_DBL_W + n];
#pragma unroll
            for (int tt = 0; tt < 8; ++tt) acc[tt] = fmaf(xs[tt][kk], w, acc[tt]);
        }
        __syncthreads();
    }
#pragma unroll
    for (int tt = 0; tt < 8; ++tt)
        g_xdp[((size_t)ks * L_SEQ + t0 + tt) * X_DBL_W + n] = acc[tt];
}

__global__ void xdbl_reduce() {
    int i = blockIdx.x * 256 + threadIdx.x;            // < 98304
    const int S = L_SEQ * X_DBL_W;
    g_xdbl[i] = g_xdp[i] + g_xdp[S + i] + g_xdp[2 * S + i] + g_xdp[3 * S + i];
}

// =====================================================================
// delta = softplus(dt @ W_dt + b_dt)
// =====================================================================
__global__ void delta_kernel(const float* __restrict__ Wdt,
                             const float* __restrict__ bdt) {
    __shared__ float dts[16][64];
    int d = blockIdx.x * 256 + threadIdx.x;
    int t0 = blockIdx.y * 16;

    for (int i = threadIdx.x; i < 16 * 64; i += 256) {
        int tt = i >> 6, kk = i & 63;
        dts[tt][kk] = g_xdbl[(t0 + tt) * X_DBL_W + kk];
    }
    __syncthreads();

    float bb = bdt[d];
    float acc[16];
#pragma unroll
    for (int tt = 0; tt < 16; ++tt) acc[tt] = bb;
#pragma unroll 4
    for (int k = 0; k < DT_RANK; ++k) {
        float w = Wdt[(size_t)k * D_INNER + d];
#pragma unroll
        for (int tt = 0; tt < 16; ++tt) acc[tt] = fmaf(dts[tt][k], w, acc[tt]);
    }
#pragma unroll
    for (int tt = 0; tt < 16; ++tt) {
        float a = acc[tt];
        float sp = (a > 20.f) ? a : log1pf(__expf(a));
        g_delta[(size_t)(t0 + tt) * D_INNER + d] = sp;
    }
}

// =====================================================================
// chunked selective scan (P1 summaries, P2 boundary states, P3 emit)
// =====================================================================
__global__ void scan_p1(const float* __restrict__ A_log) {
    int tid = threadIdx.x;
    int g = tid >> 4, n = tid & 15;
    int d = blockIdx.x * 8 + g;
    int c = blockIdx.y;

    float Aval = -__expf(A_log[d * N_STATE + n]);
    float P = 1.f, S = 0.f;
    int tbase = c * CHUNK;
#pragma unroll 8
    for (int i = 0; i < CHUNK; ++i) {
        int t = tbase + i;
        float dl = g_delta[(size_t)t * D_INNER + d];
        float u  = g_xconv[(size_t)t * D_INNER + d];
        float Bv = g_xdbl[t * X_DBL_W + DT_RANK + n];
        float dA = __expf(dl * Aval);
        S = fmaf(dA, S, dl * Bv * u);
        P *= dA;
    }
    int idx = (c * D_INNER + d) * N_STATE + n;
    g_P[idx] = P;
    g_S[idx] = S;
}

__global__ void scan_p2() {
    int dn = blockIdx.x * 256 + threadIdx.x;
    float h = 0.f;
#pragma unroll
    for (int c = 0; c < NCHUNK; ++c) {
        int idx = c * (D_INNER * N_STATE) + dn;
        g_h0[idx] = h;
        h = fmaf(g_P[idx], h, g_S[idx]);
    }
}

// P3: emit gated output directly as fp16 A-split into g_aext (GEMM2 input)
__global__ void scan_p3(const float* __restrict__ A_log,
                        const float* __restrict__ Dp) {
    int tid = threadIdx.x;
    int g = tid >> 4, n = tid & 15;
    int d = blockIdx.x * 8 + g;
    int c = blockIdx.y;

    float Aval = -__expf(A_log[d * N_STATE + n]);
    float Dd = Dp[d];
    float h = g_h0[(c * D_INNER + d) * N_STATE + n];
    int tbase = c * CHUNK;
#pragma unroll 4
    for (int i = 0; i < CHUNK; ++i) {
        int t = tbase + i;
        float dl = g_delta[(size_t)t * D_INNER + d];
        float u  = g_xconv[(size_t)t * D_INNER + d];
        float Bv = g_xdbl[t * X_DBL_W + DT_RANK + n];
        float Cv = g_xdbl[t * X_DBL_W + DT_RANK + N_STATE + n];

        float dA = __expf(dl * Aval);
        h = fmaf(dA, h, dl * Bv * u);
        float part = h * Cv;
        part += __shfl_xor_sync(0xffffffffu, part, 8, 16);
        part += __shfl_xor_sync(0xffffffffu, part, 4, 16);
        part += __shfl_xor_sync(0xffffffffu, part, 2, 16);
        part += __shfl_xor_sync(0xffffffffu, part, 1, 16);

        if (n == 0) {
            float r = g_xr[(size_t)t * 4096 + D_INNER + d];
            float sr = __fdividef(r, 1.f + __expf(-r));
            float val = (part + u * Dd) * sr;
            __half hh = __float2half(val);
            __half ll = __float2half(val - __half2float(hh));
            g_aext[(size_t)t * 4096 + d] = hh;                 // Ah
            g_aext[(size_t)t * 4096 + D_INNER + d] = ll;       // Al
        }
    }
}

// =====================================================================
// launch
// =====================================================================
template <typename T>
static T* sym_addr(const void* sym) {
    void* p = nullptr;
    cudaGetSymbolAddress(&p, sym);
    return (T*)p;
}

extern "C" void kernel_launch(void* const* d_in, const int* in_sizes, int n_in,
                              void* d_out, int out_size) {
    const float* x      = (const float*)d_in[0];
    const float* W_in   = (const float*)d_in[1];
    const float* conv_w = (const float*)d_in[2];
    const float* conv_b = (const float*)d_in[3];
    const float* W_x    = (const float*)d_in[4];
    const float* W_dt   = (const float*)d_in[5];
    const float* b_dt   = (const float*)d_in[6];
    const float* A_log  = (const float*)d_in[7];
    const float* Dvec   = (const float*)d_in[8];
    const float* W_out  = (const float*)d_in[9];
    float* out = (float*)d_out;

    cudaFuncSetAttribute(gemm_mma, cudaFuncAttributeMaxDynamicSharedMemorySize, GSMEM);

    float* xr   = sym_addr<float>(g_xr);
    float* tmp  = sym_addr<float>(g_tmp);
    __half* ae  = sym_addr<__half>(g_aext);
    __half* b1e = sym_addr<__half>(g_b1e);
    __half* b2e = sym_addr<__half>(g_b2e);

    // 0) all fp32->fp16 split conversions in one launch
    cvt_all<<<14336, 256>>>(x, W_in, W_out);

    // 1) x_and_res = x @ W_in   [1024,4096]; Kext=3072, korig=1024
    gemm_mma<<<dim3(4096 / GBN, 1024 / GBM, 1), 256, GSMEM>>>(
        ae, b1e, xr, nullptr, nullptr, nullptr, 4096, 3072, 1024, 2048, 4096);

    // 2+3) fused conv+silu+x_dbl (K-split x4) + reduce
    xdbl_conv<<<dim3(L_SEQ / 8, 4), X_DBL_W>>>(W_x, conv_w, conv_b);
    xdbl_reduce<<<L_SEQ * X_DBL_W / 256, 256>>>();

    // 4) delta
    delta_kernel<<<dim3(D_INNER / 256, L_SEQ / 16), 256>>>(W_dt, b_dt);

    // 5) chunked selective scan; p3 emits fp16-split ysc into g_aext
    scan_p1<<<dim3(D_INNER / 8, NCHUNK), 128>>>(A_log);
    scan_p2<<<D_INNER * N_STATE / 256, 256>>>();
    scan_p3<<<dim3(D_INNER / 8, NCHUNK), 128>>>(A_log, Dvec);

    // 6) out = ysc @ W_out  [1024,1024]; Kext=6144, korig=2048, split-K z=4
    gemm_mma<<<dim3(1024 / GBN, 1024 / GBM, 4), 256, GSMEM>>>(
        ae, b2e, out, tmp, tmp + 1024 * 1024, tmp + 2 * 1024 * 1024,
        1024, 6144, 2048, 4096, 1024);
    add4_kernel<<<1024 * 1024 / 1024, 256>>>(out);
}

// round 16
// speedup vs baseline: 3.8731x; 1.0311x over previous
#include <cuda_runtime.h>
#include <cuda_fp16.h>
#include <cstdint>

// ---------------- problem constants ----------------
#define L_SEQ    1024
#define D_MODEL  1024
#define D_INNER  2048
#define N_STATE  16
#define DT_RANK  64
#define X_DBL_W  96   // DT_RANK + 2*N_STATE
#define CHUNK    32
#define NCHUNK   (L_SEQ / CHUNK)   // 32

// ---------------- fp32 scratch ----------------
__device__ float g_xr[L_SEQ * 2 * D_INNER];      // x_and_res [1024,4096]
__device__ float g_xconv[L_SEQ * D_INNER];       // [1024,2048]
__device__ float g_xdbl[L_SEQ * X_DBL_W];        // [1024,96]
__device__ float g_xdp[4 * L_SEQ * X_DBL_W];     // xdbl K-split partials
__device__ float g_delta[L_SEQ * D_INNER];       // [1024,2048]
__device__ float g_tmp[3 * 1024 * 1024];         // GEMM2 split-K partials

// ---------------- chunked-scan scratch ----------------
__device__ float g_P[NCHUNK * D_INNER * N_STATE];
__device__ float g_S[NCHUNK * D_INNER * N_STATE];
__device__ float g_h0[NCHUNK * D_INNER * N_STATE];

// ---------------- fp16 split scratch ----------------
// A = [Ah | Al] (M x 2K) row-major; B = [Bh ; Bl] (2K x N) K-major
__device__ __half g_aext[1024 * 4096];           // x split, then ysc split
__device__ __half g_b1e[2048 * 4096];            // W_in split  [2*1024, 4096]
__device__ __half g_b2e[4096 * 1024];            // W_out split [2*2048, 1024]

// =====================================================================
// base-PTX helpers (compute_103-safe)
// =====================================================================
__device__ __forceinline__ uint32_t smem_u32(const void* p) {
    uint32_t a;
    asm("{ .reg .u64 t; cvta.to.shared.u64 t, %1; cvt.u32.u64 %0, t; }" : "=r"(a) : "l"(p));
    return a;
}
__device__ __forceinline__ void cp16(uint32_t s, const void* g) {
    asm volatile("cp.async.cg.shared.global [%0], [%1], 16;" :: "r"(s), "l"(g));
}
#define CP_COMMIT() asm volatile("cp.async.commit_group;" ::: "memory")

#define LDSM_X4(r0, r1, r2, r3, addr) \
    asm volatile("ldmatrix.sync.aligned.m8n8.x4.shared.b16 {%0,%1,%2,%3}, [%4];" \
        : "=r"(r0), "=r"(r1), "=r"(r2), "=r"(r3) : "r"(addr))
#define LDSM_X2_T(r0, r1, addr) \
    asm volatile("ldmatrix.sync.aligned.m8n8.x2.trans.shared.b16 {%0,%1}, [%2];" \
        : "=r"(r0), "=r"(r1) : "r"(addr))
#define MMA16816(d, a, b) \
    asm volatile("mma.sync.aligned.m16n8k16.row.col.f32.f16.f16.f32 " \
        "{%0,%1,%2,%3}, {%4,%5,%6,%7}, {%8,%9}, {%0,%1,%2,%3};" \
        : "+f"((d)[0]), "+f"((d)[1]), "+f"((d)[2]), "+f"((d)[3]) \
        : "r"((a)[0]), "r"((a)[1]), "r"((a)[2]), "r"((a)[3]), "r"((b)[0]), "r"((b)[1]))

// =====================================================================
// HMMA GEMM over extended K (3 split-terms folded into K):
//   ke<K      : Ah*Bh   kA=ke      kB=ke
//   K<=ke<2K  : Ah*Bl   kA=ke-K    kB=ke
//   2K<=ke<3K : Al*Bh   kA=ke-K    kB=ke-2K
// A row-major [M,2K] (lda), B K-major [2K,N] (ldb).
// tile 128x128x64, 8 warps, 3-stage cp.async pipeline (1 sync/iter).
// split-K over gridDim.z -> C0..C3.
// =====================================================================
#define GBM 128
#define GBN 128
#define A_STR 144                  // bytes: 64 halves + 8 pad
#define B_STR 272                  // bytes: 128 halves + 8 pad
#define A_BYTES (128 * A_STR)      // 18432
#define B_BYTES (64 * B_STR)       // 17408
#define STAGE_B (A_BYTES + B_BYTES)   // 35840
#define NSTAGE 3
#define GSMEM (NSTAGE * STAGE_B)      // 107520

__global__ void __launch_bounds__(256, 2) gemm_mma(
    const __half* __restrict__ A, const __half* __restrict__ B,
    float* __restrict__ C0, float* __restrict__ C1,
    float* __restrict__ C2, float* __restrict__ C3,
    int N, int Kext, int korig, int lda, int ldb) {
    extern __shared__ __align__(16) char smem[];
    const uint32_t sbase = smem_u32(smem);
    const int tid = threadIdx.x;
    const int lane = tid & 31, wid = tid >> 5;
    const int m0 = blockIdx.y * GBM, n0 = blockIdx.x * GBN;
    const int z = blockIdx.z;
    const int Kz = Kext / gridDim.z;
    const int ke0 = z * Kz;
    float* C = (z == 0) ? C0 : (z == 1) ? C1 : (z == 2) ? C2 : C3;

    const __half* Ag = A + (size_t)m0 * lda;
    const __half* Bg = B + n0;

    const int wm = (wid & 1) * 64;
    const int wn = (wid >> 1) * 32;

    float acc[4][4][4];
#pragma unroll
    for (int i = 0; i < 4; ++i)
#pragma unroll
        for (int j = 0; j < 4; ++j)
#pragma unroll
            for (int q = 0; q < 4; ++q) acc[i][j][q] = 0.f;

    const int nIter = Kz >> 6;

    auto load_tile = [&](int it, int stage) {
        int kt = ke0 + (it << 6);
        int kA = (kt < korig) ? kt : kt - korig;
        int kB = (kt < 2 * korig) ? kt : kt - 2 * korig;
        uint32_t sA = sbase + stage * STAGE_B;
        uint32_t sB = sA + A_BYTES;
#pragma unroll
        for (int c = tid; c < 2048; c += 256) {
            if (c < 1024) {
                int r = c >> 3, col = (c & 7) * 16;
                cp16(sA + r * A_STR + col,
                     (const char*)(Ag + (size_t)r * lda + kA) + col);
            } else {
                int cc = c - 1024;
                int r = cc >> 4, col = (cc & 15) * 16;
                cp16(sB + r * B_STR + col,
                     (const char*)(Bg + (size_t)(kB + r) * ldb) + col);
            }
        }
    };

    // prologue: stages 0 and 1 in flight
    load_tile(0, 0);
    CP_COMMIT();
    load_tile(1, 1);
    CP_COMMIT();

    const uint32_t aOff = (wm + (lane & 15)) * A_STR + (lane >> 4) * 16;
    const uint32_t bOff = (lane & 15) * B_STR + wn * 2;

    int cs = 0;           // compute stage = it % 3
    int ls = 2;           // load stage    = (it+2) % 3
    for (int it = 0; it < nIter; ++it) {
        asm volatile("cp.async.wait_group 1;" ::: "memory");
        __syncthreads();

        if (it + 2 < nIter) load_tile(it + 2, ls);
        CP_COMMIT();

        uint32_t sA = sbase + cs * STAGE_B + aOff;
        uint32_t sB = sbase + cs * STAGE_B + A_BYTES + bOff;
#pragma unroll
        for (int ks = 0; ks < 4; ++ks) {
            uint32_t a[4][4], b[4][2];
#pragma unroll
            for (int mt = 0; mt < 4; ++mt)
                LDSM_X4(a[mt][0], a[mt][1], a[mt][2], a[mt][3],
                        sA + mt * (16 * A_STR) + ks * 32);
#pragma unroll
            for (int nt = 0; nt < 4; ++nt)
                LDSM_X2_T(b[nt][0], b[nt][1], sB + ks * (16 * B_STR) + nt * 16);
#pragma unroll
            for (int mt = 0; mt < 4; ++mt)
#pragma unroll
                for (int nt = 0; nt < 4; ++nt)
                    MMA16816(acc[mt][nt], a[mt], b[nt]);
        }
        cs = (cs == 2) ? 0 : cs + 1;
        ls = (ls == 2) ? 0 : ls + 1;
    }

    const int qr = lane >> 2, qc = (lane & 3) * 2;
#pragma unroll
    for (int mt = 0; mt < 4; ++mt) {
        int row = m0 + wm + mt * 16 + qr;
#pragma unroll
        for (int nt = 0; nt < 4; ++nt) {
            int col = n0 + wn + nt * 8 + qc;
            *(float2*)(C + (size_t)row * N + col) =
                make_float2(acc[mt][nt][0], acc[mt][nt][1]);
            *(float2*)(C + (size_t)(row + 8) * N + col) =
                make_float2(acc[mt][nt][2], acc[mt][nt][3]);
        }
    }
}

// out += t0 + t1 + t2   (GEMM2 split-K reduction, 1024x1024)
__global__ void add4_kernel(float* __restrict__ out) {
    int i = (blockIdx.x * 256 + threadIdx.x) * 4;
    float4 a = *(const float4*)(out + i);
    float4 b = *(const float4*)(g_tmp + i);
    float4 c = *(const float4*)(g_tmp + 1024 * 1024 + i);
    float4 d = *(const float4*)(g_tmp + 2 * 1024 * 1024 + i);
    a.x += b.x + c.x + d.x; a.y += b.y + c.y + d.y;
    a.z += b.z + c.z + d.z; a.w += b.w + c.w + d.w;
    *(float4*)(out + i) = a;
}

// =====================================================================
// merged conversion kernel (one launch)
// =====================================================================
__device__ __forceinline__ void split2(float2 v, __half2& hh, __half2& ll) {
    __half h0 = __float2half(v.x), h1 = __float2half(v.y);
    hh.x = h0; hh.y = h1;
    ll.x = __float2half(v.x - __half2float(h0));
    ll.y = __float2half(v.y - __half2float(h1));
}

__global__ void cvt_all(const float* __restrict__ x,
                        const float* __restrict__ W_in,
                        const float* __restrict__ W_out) {
    int b = blockIdx.x;
    if (b < 2048) {
        int i2 = (b * 256 + threadIdx.x) * 2;          // < 1M
        const int C = 1024;
        int r = i2 >> 10, c = i2 & 1023;
        __half2 hh, ll;
        split2(*(const float2*)(x + i2), hh, ll);
        __half* row = g_aext + (size_t)r * 2 * C;
        *(__half2*)(row + c) = hh;
        *(__half2*)(row + C + c) = ll;
    } else if (b < 10240) {
        int i2 = ((b - 2048) * 256 + threadIdx.x) * 2; // < 4M
        const int KN = 1024 * 4096;
        __half2 hh, ll;
        split2(*(const float2*)(W_in + i2), hh, ll);
        *(__half2*)(g_b1e + i2) = hh;
        *(__half2*)(g_b1e + KN + i2) = ll;
    } else {
        int i2 = ((b - 10240) * 256 + threadIdx.x) * 2; // < 2M
        const int KN = 2048 * 1024;
        __half2 hh, ll;
        split2(*(const float2*)(W_out + i2), hh, ll);
        *(__half2*)(g_b2e + i2) = hh;
        *(__half2*)(g_b2e + KN + i2) = ll;
    }
}

// =====================================================================
// fused: causal depthwise conv (K=4) + SiLU  +  x_dbl partial GEMM
// =====================================================================
__global__ void xdbl_conv(const float* __restrict__ Wx,
                          const float* __restrict__ conv_w,
                          const float* __restrict__ conv_b) {
    __shared__ float xs[8][256];
    int t0 = blockIdx.x * 8;
    int ks = blockIdx.y;                               // 0..3
    int n = threadIdx.x;                               // 0..95
    float acc[8];
#pragma unroll
    for (int tt = 0; tt < 8; ++tt) acc[tt] = 0.f;

    int kbeg = ks * 512;
    for (int k0 = kbeg; k0 < kbeg + 512; k0 += 256) {
        for (int i = n; i < 8 * 256; i += 96) {
            int tt = i >> 8, kk = i & 255;
            int t = t0 + tt, d = k0 + kk;
            float4 w = *(const float4*)(conv_w + d * 4);
            float s = conv_b[d];
            if (t >= 3) s += g_xr[(size_t)(t - 3) * 4096 + d] * w.x;
            if (t >= 2) s += g_xr[(size_t)(t - 2) * 4096 + d] * w.y;
            if (t >= 1) s += g_xr[(size_t)(t - 1) * 4096 + d] * w.z;
            s += g_xr[(size_t)t * 4096 + d] * w.w;
            float v = __fdividef(s, 1.f + __expf(-s));
            xs[tt][kk] = v;
            g_xconv[(size_t)t * D_INNER + d] = v;
        }
        __syncthreads();
#pragma unroll 8
        for (int kk = 0; kk < 256; ++kk) {
            float w = Wx[(size_t)(k0 + kk) * X_DBL_W + n];
#pragma unroll
            for (int tt = 0; tt < 8; ++tt) acc[tt] = fmaf(xs[tt][kk], w, acc[tt]);
        }
        __syncthreads();
    }
#pragma unroll
    for (int tt = 0; tt < 8; ++tt)
        g_xdp[((size_t)ks * L_SEQ + t0 + tt) * X_DBL_W + n] = acc[tt];
}

__global__ void xdbl_reduce() {
    int i = blockIdx.x * 256 + threadIdx.x;            // < 98304
    const int S = L_SEQ * X_DBL_W;
    g_xdbl[i] = g_xdp[i] + g_xdp[S + i] + g_xdp[2 * S + i] + g_xdp[3 * S + i];
}

// =====================================================================
// delta = softplus(dt @ W_dt + b_dt)
// =====================================================================
__global__ void delta_kernel(const float* __restrict__ Wdt,
                             const float* __restrict__ bdt) {
    __shared__ float dts[16][64];
    int d = blockIdx.x * 256 + threadIdx.x;
    int t0 = blockIdx.y * 16;

    for (int i = threadIdx.x; i < 16 * 64; i += 256) {
        int tt = i >> 6, kk = i & 63;
        dts[tt][kk] = g_xdbl[(t0 + tt) * X_DBL_W + kk];
    }
    __syncthreads();

    float bb = bdt[d];
    float acc[16];
#pragma unroll
    for (int tt = 0; tt < 16; ++tt) acc[tt] = bb;
#pragma unroll 4
    for (int k = 0; k < DT_RANK; ++k) {
        float w = Wdt[(size_t)k * D_INNER + d];
#pragma unroll
        for (int tt = 0; tt < 16; ++tt) acc[tt] = fmaf(dts[tt][k], w, acc[tt]);
    }
#pragma unroll
    for (int tt = 0; tt < 16; ++tt) {
        float a = acc[tt];
        float sp = (a > 20.f) ? a : log1pf(__expf(a));
        g_delta[(size_t)(t0 + tt) * D_INNER + d] = sp;
    }
}

// =====================================================================
// chunked selective scan — ONE THREAD PER CHANNEL d (no shfl, no
// thread redundancy). h/P/S[16] live in registers.
// =====================================================================
__global__ void scan_p1(const float* __restrict__ A_log) {
    int d = blockIdx.x * 256 + threadIdx.x;            // 0..2047
    int c = blockIdx.y;

    float Av[N_STATE], P[N_STATE], S[N_STATE];
#pragma unroll
    for (int n = 0; n < N_STATE; ++n) {
        Av[n] = -__expf(A_log[d * N_STATE + n]);
        P[n] = 1.f;
        S[n] = 0.f;
    }
    int tbase = c * CHUNK;
    for (int i = 0; i < CHUNK; ++i) {
        int t = tbase + i;
        float dl = g_delta[(size_t)t * D_INNER + d];
        float u  = g_xconv[(size_t)t * D_INNER + d];
        float bu = dl * u;
        const float* xb = g_xdbl + t * X_DBL_W + DT_RANK;
#pragma unroll
        for (int n = 0; n < N_STATE; ++n) {
            float dA = __expf(dl * Av[n]);
            S[n] = fmaf(dA, S[n], bu * xb[n]);
            P[n] *= dA;
        }
    }
    float* Pd = g_P + ((size_t)c * D_INNER + d) * N_STATE;
    float* Sd = g_S + ((size_t)c * D_INNER + d) * N_STATE;
#pragma unroll
    for (int n = 0; n < N_STATE; n += 4) {
        *(float4*)(Pd + n) = make_float4(P[n], P[n + 1], P[n + 2], P[n + 3]);
        *(float4*)(Sd + n) = make_float4(S[n], S[n + 1], S[n + 2], S[n + 3]);
    }
}

__global__ void scan_p2() {
    int dn = blockIdx.x * 256 + threadIdx.x;
    float h = 0.f;
#pragma unroll
    for (int c = 0; c < NCHUNK; ++c) {
        int idx = c * (D_INNER * N_STATE) + dn;
        g_h0[idx] = h;
        h = fmaf(g_P[idx], h, g_S[idx]);
    }
}

// P3: per-d thread; emits gated output as fp16 A-split into g_aext
__global__ void scan_p3(const float* __restrict__ A_log,
                        const float* __restrict__ Dp) {
    int d = blockIdx.x * 256 + threadIdx.x;            // 0..2047
    int c = blockIdx.y;

    float Av[N_STATE], h[N_STATE];
    const float* h0 = g_h0 + ((size_t)c * D_INNER + d) * N_STATE;
#pragma unroll
    for (int n = 0; n < N_STATE; ++n) {
        Av[n] = -__expf(A_log[d * N_STATE + n]);
        h[n] = h0[n];
    }
    float Dd = Dp[d];
    int tbase = c * CHUNK;
    for (int i = 0; i < CHUNK; ++i) {
        int t = tbase + i;
        float dl = g_delta[(size_t)t * D_INNER + d];
        float u  = g_xconv[(size_t)t * D_INNER + d];
        float bu = dl * u;
        const float* xb = g_xdbl + t * X_DBL_W + DT_RANK;
        float y = 0.f;
#pragma unroll
        for (int n = 0; n < N_STATE; ++n) {
            float dA = __expf(dl * Av[n]);
            h[n] = fmaf(dA, h[n], bu * xb[n]);
            y = fmaf(h[n], xb[N_STATE + n], y);
        }
        float r = g_xr[(size_t)t * 4096 + D_INNER + d];
        float sr = __fdividef(r, 1.f + __expf(-r));
        float val = (y + u * Dd) * sr;
        __half hh = __float2half(val);
        __half ll = __float2half(val - __half2float(hh));
        g_aext[(size_t)t * 4096 + d] = hh;                 // Ah
        g_aext[(size_t)t * 4096 + D_INNER + d] = ll;       // Al
    }
}

// =====================================================================
// launch
// =====================================================================
template <typename T>
static T* sym_addr(const void* sym) {
    void* p = nullptr;
    cudaGetSymbolAddress(&p, sym);
    return (T*)p;
}

extern "C" void kernel_launch(void* const* d_in, const int* in_sizes, int n_in,
                              void* d_out, int out_size) {
    const float* x      = (const float*)d_in[0];
    const float* W_in   = (const float*)d_in[1];
    const float* conv_w = (const float*)d_in[2];
    const float* conv_b = (const float*)d_in[3];
    const float* W_x    = (const float*)d_in[4];
    const float* W_dt   = (const float*)d_in[5];
    const float* b_dt   = (const float*)d_in[6];
    const float* A_log  = (const float*)d_in[7];
    const float* Dvec   = (const float*)d_in[8];
    const float* W_out  = (const float*)d_in[9];
    float* out = (float*)d_out;

    cudaFuncSetAttribute(gemm_mma, cudaFuncAttributeMaxDynamicSharedMemorySize, GSMEM);

    float* xr   = sym_addr<float>(g_xr);
    float* tmp  = sym_addr<float>(g_tmp);
    __half* ae  = sym_addr<__half>(g_aext);
    __half* b1e = sym_addr<__half>(g_b1e);
    __half* b2e = sym_addr<__half>(g_b2e);

    // 0) all fp32->fp16 split conversions in one launch
    cvt_all<<<14336, 256>>>(x, W_in, W_out);

    // 1) x_and_res = x @ W_in   [1024,4096]; Kext=3072, korig=1024
    gemm_mma<<<dim3(4096 / GBN, 1024 / GBM, 1), 256, GSMEM>>>(
        ae, b1e, xr, nullptr, nullptr, nullptr, 4096, 3072, 1024, 2048, 4096);

    // 2+3) fused conv+silu+x_dbl (K-split x4) + reduce
    xdbl_conv<<<dim3(L_SEQ / 8, 4), X_DBL_W>>>(W_x, conv_w, conv_b);
    xdbl_reduce<<<L_SEQ * X_DBL_W / 256, 256>>>();

    // 4) delta
    delta_kernel<<<dim3(D_INNER / 256, L_SEQ / 16), 256>>>(W_dt, b_dt);

    // 5) chunked selective scan (per-d threads); p3 emits fp16-split ysc
    scan_p1<<<dim3(D_INNER / 256, NCHUNK), 256>>>(A_log);
    scan_p2<<<D_INNER * N_STATE / 256, 256>>>();
    scan_p3<<<dim3(D_INNER / 256, NCHUNK), 256>>>(A_log, Dvec);

    // 6) out = ysc @ W_out  [1024,1024]; Kext=6144, korig=2048, split-K z=4
    gemm_mma<<<dim3(1024 / GBN, 1024 / GBM, 4), 256, GSMEM>>>(
        ae, b2e, out, tmp, tmp + 1024 * 1024, tmp + 2 * 1024 * 1024,
        1024, 6144, 2048, 4096, 1024);
    add4_kernel<<<1024 * 1024 / 1024, 256>>>(out);
}